// round 3
// baseline (speedup 1.0000x reference)
#include <cuda_runtime.h>
#include <math.h>

// Problem constants
#define Bsz   8
#define Ntok  4096
#define Cch   512
#define NHh   8
#define HDd   64
#define MAXPC 321
#define EPSC  1e-6f

// ---------------------------------------------------------------------------
// Scratch (device globals -- allocation-free per harness rules)
// ---------------------------------------------------------------------------
static __device__ float g_QQ[Bsz*NHh*Ntok*128];     // [b][h][n][128] = [q_pos|q_neg]
static __device__ float g_KK[Bsz*NHh*Ntok*128];     // [b][h][n][128] = [k_pos|k_neg]
static __device__ float g_G [Bsz*Ntok*Cch];         // gate, (B,N,C)
static __device__ float g_V [Bsz*Ntok*Cch];         // v, (B,N,C) c = h*64+d
static __device__ float g_XA[Bsz*Ntok*Cch];         // attention out -> (xa+vd)*g in place
static __device__ float g_VD[Bsz*Ntok*Cch];         // depthwise conv out (B,N,C)
static __device__ float g_PKV[Bsz*NHh*8*128*64];    // partial kk^T v per n-chunk
static __device__ float g_PKS[Bsz*NHh*8*128];       // partial kk colsums per n-chunk
static __device__ float g_KVC[Bsz*NHh*128*66];      // [d][0:32]=kv1,[32:64]=kv2rot,[64]=km,[65]=km_rot
static __device__ float2 g_Z [Bsz*NHh*Ntok];        // per-token (q.km, q.km_rot)
static __device__ float g_scale[Cch];
static __device__ float g_power[Cch];

// ---------------------------------------------------------------------------
// K0: precompute softplus(scale_p), 1+4*sigmoid(power_p)
// ---------------------------------------------------------------------------
__global__ void prep_kernel(const float* __restrict__ scale_p,
                            const float* __restrict__ power_p) {
    int i = threadIdx.x;
    if (i < Cch) {
        float sp = scale_p[i];
        g_scale[i] = (sp > 20.f) ? sp : log1pf(expf(sp));
        float pp = power_p[i];
        g_power[i] = 1.0f + 4.0f / (1.0f + expf(-pp));
    }
}

// ---------------------------------------------------------------------------
// SGEMM: C[m][n] = sum_k X[m][k]*W[n][k], K=512, BM=BN=128, BK=16, 8x8/thread
// MODE 0: qg (fused q scale+pow -> g_QQ, gate -> g_G)
// MODE 1: kv (fused +pos_emb, scale+pow -> g_KK, v -> g_V)
// MODE 2: proj (X = g_XA, +bias -> out)
// ---------------------------------------------------------------------------
template<int MODE>
__global__ __launch_bounds__(256) void gemm_k512(
    const float* __restrict__ Xin, const float* __restrict__ W,
    const float* __restrict__ aux, float* __restrict__ out)
{
    __shared__ float As[16][132];
    __shared__ float Bs[16][132];
    const int bm = blockIdx.y * 128;
    const int bn = blockIdx.x * 128;
    const int tid = threadIdx.x;
    const int tm = (tid >> 4) << 3;
    const int tn = (tid & 15) << 3;

    const float* X = (MODE == 2) ? g_XA : Xin;

    float acc[8][8];
    #pragma unroll
    for (int i = 0; i < 8; i++)
        #pragma unroll
        for (int j = 0; j < 8; j++) acc[i][j] = 0.f;

    const float* Xp = X + (size_t)bm * 512;
    const float* Wp = W + (size_t)bn * 512;

    for (int k0 = 0; k0 < 512; k0 += 16) {
        #pragma unroll
        for (int l = 0; l < 2; l++) {
            int idx = tid + l * 256;
            int row = idx >> 2;
            int kc  = (idx & 3) << 2;
            float4 av = *(const float4*)(Xp + (size_t)row * 512 + k0 + kc);
            As[kc+0][row] = av.x; As[kc+1][row] = av.y;
            As[kc+2][row] = av.z; As[kc+3][row] = av.w;
            float4 bv = *(const float4*)(Wp + (size_t)row * 512 + k0 + kc);
            Bs[kc+0][row] = bv.x; Bs[kc+1][row] = bv.y;
            Bs[kc+2][row] = bv.z; Bs[kc+3][row] = bv.w;
        }
        __syncthreads();
        #pragma unroll
        for (int kk = 0; kk < 16; kk++) {
            float a[8], b[8];
            #pragma unroll
            for (int i = 0; i < 8; i++) a[i] = As[kk][tm + i];
            #pragma unroll
            for (int j = 0; j < 8; j++) b[j] = Bs[kk][tn + j];
            #pragma unroll
            for (int i = 0; i < 8; i++)
                #pragma unroll
                for (int j = 0; j < 8; j++)
                    acc[i][j] = fmaf(a[i], b[j], acc[i][j]);
        }
        __syncthreads();
    }

    if (MODE == 2) {
        #pragma unroll
        for (int i = 0; i < 8; i++) {
            int m = bm + tm + i;
            #pragma unroll
            for (int j = 0; j < 8; j++) {
                int c = bn + tn + j;
                out[(size_t)m * 512 + c] = acc[i][j] + aux[c];
            }
        }
        return;
    }

    if (bn < 512) {
        // q / k half: fuse scale, (for kv) pos-emb, safe_pow into head layout
        #pragma unroll
        for (int i = 0; i < 8; i++) {
            int m = bm + tm + i;
            int bz = m >> 12, tok = m & 4095;
            #pragma unroll
            for (int j = 0; j < 8; j++) {
                int c = bn + tn + j;
                float val = acc[i][j];
                if (MODE == 1)
                    val += aux[(size_t)(tok % MAXPC) * 512 + c];
                val = val / g_scale[c];
                float p = g_power[c];
                float aq = fabsf(val);
                float r = (aq > 0.f) ? powf(aq, p) : 0.f;
                int h = c >> 6, d = c & 63;
                float* dst = (MODE == 0 ? g_QQ : g_KK)
                           + ((size_t)((bz * NHh + h) * Ntok + tok)) * 128;
                dst[d]      = (val > 0.f) ? r : 0.f;
                dst[64 + d] = (val < 0.f) ? r : 0.f;
            }
        }
    } else {
        // g / v half
        #pragma unroll
        for (int i = 0; i < 8; i++) {
            int m = bm + tm + i;
            float* dst = (MODE == 0 ? g_G : g_V) + (size_t)m * 512 + (bn - 512);
            #pragma unroll
            for (int j = 0; j < 8; j++)
                dst[tn + j] = acc[i][j];
        }
    }
}

// ---------------------------------------------------------------------------
// K3a: per (chunk, b*h) partial KV = KK^T @ Vhead over 512 tokens + colsums
// ---------------------------------------------------------------------------
__global__ __launch_bounds__(256) void kv_partial() {
    const int chunk = blockIdx.x;   // 0..7
    const int bh    = blockIdx.y;   // 0..63
    const int b = bh >> 3, h = bh & 7;
    __shared__ float KKs[32][128];
    __shared__ float Vs[32][64];
    const int tid = threadIdx.x;
    const int d0 = (tid & 31) << 2;
    const int e0 = (tid >> 5) << 3;

    float acc[4][8];
    #pragma unroll
    for (int i = 0; i < 4; i++)
        #pragma unroll
        for (int j = 0; j < 8; j++) acc[i][j] = 0.f;
    float ks = 0.f;

    const float* KKb = g_KK + ((size_t)bh * Ntok + (size_t)chunk * 512) * 128;
    const float* Vb  = g_V + ((size_t)(b * Ntok + chunk * 512)) * Cch + h * 64;

    for (int t = 0; t < 16; t++) {
        #pragma unroll
        for (int l = 0; l < 4; l++) {
            int fidx = tid + l * 256;              // 0..1023 float4s
            int r = fidx >> 5, d4 = (fidx & 31) << 2;
            *(float4*)&KKs[r][d4] =
                *(const float4*)(KKb + (size_t)(t * 32 + r) * 128 + d4);
        }
        #pragma unroll
        for (int l = 0; l < 2; l++) {
            int fidx = tid + l * 256;              // 0..511 float4s
            int r = fidx >> 4, e4 = (fidx & 15) << 2;
            *(float4*)&Vs[r][e4] =
                *(const float4*)(Vb + (size_t)(t * 32 + r) * Cch + e4);
        }
        __syncthreads();
        #pragma unroll
        for (int r = 0; r < 32; r++) {
            float4 a = *(float4*)&KKs[r][d0];
            float4 b0 = *(float4*)&Vs[r][e0];
            float4 b1 = *(float4*)&Vs[r][e0 + 4];
            float av[4] = {a.x, a.y, a.z, a.w};
            float bv[8] = {b0.x, b0.y, b0.z, b0.w, b1.x, b1.y, b1.z, b1.w};
            #pragma unroll
            for (int i = 0; i < 4; i++)
                #pragma unroll
                for (int j = 0; j < 8; j++)
                    acc[i][j] = fmaf(av[i], bv[j], acc[i][j]);
        }
        if (tid < 128) {
            float s = 0.f;
            #pragma unroll
            for (int r = 0; r < 32; r++) s += KKs[r][tid];
            ks += s;
        }
        __syncthreads();
    }

    float* P = g_PKV + ((size_t)(bh * 8 + chunk) * 128) * 64;
    #pragma unroll
    for (int i = 0; i < 4; i++)
        #pragma unroll
        for (int j = 0; j < 8; j++)
            P[(size_t)(d0 + i) * 64 + e0 + j] = acc[i][j];
    if (tid < 128)
        g_PKS[(size_t)(bh * 8 + chunk) * 128 + tid] = ks;
}

// ---------------------------------------------------------------------------
// K3b: reduce chunks, build KVC with the opp-rotation folded in
// KVC[d][e<32]  = KV[d][e]/N            (kv1)
// KVC[d][e>=32] = KV[(d+64)%128][e]/N   (kv2, rotated so x_opp = QQ @ col)
// KVC[d][64] = km[d], KVC[d][65] = km[(d+64)%128]
// ---------------------------------------------------------------------------
__global__ __launch_bounds__(256) void kv_reduce() {
    const int bh = blockIdx.x;
    const int tid = threadIdx.x;
    const float inv_n = 1.0f / (float)Ntok;
    for (int p = tid; p < 128 * 64; p += 256) {
        int d = p >> 6, e = p & 63;
        int dsrc = (e < 32) ? d : ((d + 64) & 127);
        float s = 0.f;
        #pragma unroll
        for (int c2 = 0; c2 < 8; c2++)
            s += g_PKV[((size_t)(bh * 8 + c2) * 128 + dsrc) * 64 + e];
        g_KVC[(size_t)bh * (128 * 66) + d * 66 + e] = s * inv_n;
    }
    if (tid < 128) {
        int d = tid, dr = (d + 64) & 127;
        float s1 = 0.f, s2 = 0.f;
        #pragma unroll
        for (int c2 = 0; c2 < 8; c2++) {
            s1 += g_PKS[(size_t)(bh * 8 + c2) * 128 + d];
            s2 += g_PKS[(size_t)(bh * 8 + c2) * 128 + dr];
        }
        g_KVC[(size_t)bh * (128 * 66) + d * 66 + 64] = s1 * inv_n;
        g_KVC[(size_t)bh * (128 * 66) + d * 66 + 65] = s2 * inv_n;
    }
}

// ---------------------------------------------------------------------------
// K4a: per-token z dots: z1raw = QQ.km, z2raw = QQ.km_rot
// ---------------------------------------------------------------------------
__global__ __launch_bounds__(256) void z_kernel() {
    const int bh = blockIdx.y;
    const int tile = blockIdx.x;   // 16 tiles x 256 tokens
    __shared__ float km[128], km2[128];
    const int tid = threadIdx.x;
    const float* __restrict__ KVCb = g_KVC + (size_t)bh * (128 * 66);
    if (tid < 128) {
        km [tid] = KVCb[tid * 66 + 64];
        km2[tid] = KVCb[tid * 66 + 65];
    }
    __syncthreads();
    const int warp = tid >> 5, lane = tid & 31;
    for (int it = 0; it < 32; it++) {
        int tok = tile * 256 + warp * 32 + it;
        float4 qv = *(const float4*)(g_QQ + ((size_t)bh * Ntok + tok) * 128 + lane * 4);
        int l4 = lane * 4;
        float p1 = qv.x*km [l4] + qv.y*km [l4+1] + qv.z*km [l4+2] + qv.w*km [l4+3];
        float p2 = qv.x*km2[l4] + qv.y*km2[l4+1] + qv.z*km2[l4+2] + qv.w*km2[l4+3];
        #pragma unroll
        for (int o = 16; o > 0; o >>= 1) {
            p1 += __shfl_down_sync(0xffffffffu, p1, o);
            p2 += __shfl_down_sync(0xffffffffu, p2, o);
        }
        if (lane == 0)
            g_Z[(size_t)bh * Ntok + tok] = make_float2(p1, p2);
    }
}

// ---------------------------------------------------------------------------
// K4: X = QQ(4096x128) @ KVC(128x64) per (b,h), epilogue divides by (z+eps)
// ---------------------------------------------------------------------------
__global__ __launch_bounds__(256) void attn_apply() {
    const int bh = blockIdx.y;
    const int m0 = blockIdx.x * 128;
    const int b = bh >> 3, h = bh & 7;
    __shared__ float As[128][36];   // [row][k-in-slab]
    __shared__ float Bs[32][64];
    const int tid = threadIdx.x;
    const int tm = (tid >> 4) << 3;
    const int tn = (tid & 15) << 2;

    float acc[8][4];
    #pragma unroll
    for (int i = 0; i < 8; i++)
        #pragma unroll
        for (int j = 0; j < 4; j++) acc[i][j] = 0.f;

    const float* Qb = g_QQ + ((size_t)bh * Ntok + m0) * 128;
    const float* KVCb = g_KVC + (size_t)bh * (128 * 66);

    for (int k0 = 0; k0 < 128; k0 += 32) {
        #pragma unroll
        for (int l = 0; l < 4; l++) {
            int fidx = tid + l * 256;          // 1024 float4s
            int row = fidx >> 3, kc = (fidx & 7) << 2;
            *(float4*)&As[row][kc] =
                *(const float4*)(Qb + (size_t)row * 128 + k0 + kc);
        }
        #pragma unroll
        for (int l = 0; l < 8; l++) {
            int idx = tid + l * 256;           // 2048 floats
            int kk = idx >> 6, n = idx & 63;
            Bs[kk][n] = KVCb[(k0 + kk) * 66 + n];
        }
        __syncthreads();
        #pragma unroll
        for (int kk = 0; kk < 32; kk++) {
            float4 bv = *(float4*)&Bs[kk][tn];
            #pragma unroll
            for (int i = 0; i < 8; i++) {
                float a = As[tm + i][kk];
                acc[i][0] = fmaf(a, bv.x, acc[i][0]);
                acc[i][1] = fmaf(a, bv.y, acc[i][1]);
                acc[i][2] = fmaf(a, bv.z, acc[i][2]);
                acc[i][3] = fmaf(a, bv.w, acc[i][3]);
            }
        }
        __syncthreads();
    }

    #pragma unroll
    for (int i = 0; i < 8; i++) {
        int m = m0 + tm + i;
        float2 z = g_Z[(size_t)bh * Ntok + m];
        float zv = (tn < 32) ? z.x : z.y;
        float inv = 1.0f / (zv + EPSC);
        float* o = g_XA + ((size_t)(b * Ntok + m)) * Cch + h * 64 + tn;
        #pragma unroll
        for (int j = 0; j < 4; j++)
            o[j] = acc[i][j] * inv;
    }
}

// ---------------------------------------------------------------------------
// K5: depthwise 5x5 conv over the (c2, y, x2) view of v.
//   input:  c2 = h*8 + n/512, y = (n%512)*8 + d/8, x2 = d%8
//   output: cc = c2*8 + y/512, nn = (y%512)*8 + x2 -> VD[b][nn][cc]
// ---------------------------------------------------------------------------
__global__ __launch_bounds__(256) void dwconv(const float* __restrict__ Wc,
                                              const float* __restrict__ Bc) {
    const int ytile = blockIdx.x;   // 32 tiles of 128 rows
    const int c2 = blockIdx.y;      // 64
    const int b  = blockIdx.z;      // 8
    __shared__ float sIn[132][12];
    __shared__ float sW[25];
    __shared__ float sB;
    const int tid = threadIdx.x;
    if (tid < 25) sW[tid] = Wc[c2 * 25 + tid];
    if (tid == 25) sB = Bc[c2];
    const int y0 = ytile * 128;
    const int h = c2 >> 3;
    const int nhi = (c2 & 7) * 512;

    for (int idx = tid; idx < 132 * 12; idx += 256) {
        int sy = idx / 12, sx = idx % 12;
        int yy = y0 - 2 + sy;
        int xx = sx - 2;
        float v = 0.f;
        if (xx >= 0 && xx < 8 && yy >= 0 && yy < 4096) {
            int n = nhi + (yy >> 3);
            int d = ((yy & 7) << 3) + xx;
            v = g_V[((size_t)(b * Ntok + n)) * Cch + h * 64 + d];
        }
        sIn[sy][sx] = v;
    }
    __syncthreads();

    const int x2 = tid & 7;
    const int yl0 = tid >> 3;       // 0..31
    #pragma unroll
    for (int j = 0; j < 4; j++) {
        int yl = yl0 + j * 32;
        float a = sB;
        #pragma unroll
        for (int dy = 0; dy < 5; dy++)
            #pragma unroll
            for (int dx = 0; dx < 5; dx++)
                a = fmaf(sW[dy * 5 + dx], sIn[yl + dy][x2 + dx], a);
        int y = y0 + yl;
        int cc = c2 * 8 + (y >> 9);
        int nn = ((y & 511) << 3) + x2;
        g_VD[((size_t)(b * Ntok + nn)) * Cch + cc] = a;
    }
}

// ---------------------------------------------------------------------------
// K5b: XA = (XA + VD) * G   (in place; becomes proj input)
// ---------------------------------------------------------------------------
__global__ __launch_bounds__(256) void fuse_kernel() {
    size_t i = (size_t)blockIdx.x * 256 + threadIdx.x;   // float4 index
    float4 xa = ((const float4*)g_XA)[i];
    float4 vd = ((const float4*)g_VD)[i];
    float4 g  = ((const float4*)g_G)[i];
    float4 r;
    r.x = (xa.x + vd.x) * g.x;
    r.y = (xa.y + vd.y) * g.y;
    r.z = (xa.z + vd.z) * g.z;
    r.w = (xa.w + vd.w) * g.w;
    ((float4*)g_XA)[i] = r;
}

// ---------------------------------------------------------------------------
extern "C" void kernel_launch(void* const* d_in, const int* in_sizes, int n_in,
                              void* d_out, int out_size) {
    const float* x       = (const float*)d_in[0];
    const float* qg_w    = (const float*)d_in[1];
    const float* kv_w    = (const float*)d_in[2];
    const float* proj_w  = (const float*)d_in[3];
    const float* proj_b  = (const float*)d_in[4];
    const float* power_p = (const float*)d_in[5];
    const float* scale_p = (const float*)d_in[6];
    const float* pos_emb = (const float*)d_in[7];
    const float* dwc_w   = (const float*)d_in[8];
    const float* dwc_b   = (const float*)d_in[9];
    float* out = (float*)d_out;

    prep_kernel<<<1, 512>>>(scale_p, power_p);
    gemm_k512<0><<<dim3(8, 256), 256>>>(x, qg_w, nullptr, nullptr);
    gemm_k512<1><<<dim3(8, 256), 256>>>(x, kv_w, pos_emb, nullptr);
    kv_partial<<<dim3(8, 64), 256>>>();
    kv_reduce<<<64, 256>>>();
    z_kernel<<<dim3(16, 64), 256>>>();
    attn_apply<<<dim3(32, 64), 256>>>();
    dwconv<<<dim3(32, 64, 8), 256>>>(dwc_w, dwc_b);
    fuse_kernel<<<(Bsz * Ntok * Cch / 4) / 256, 256>>>();
    gemm_k512<2><<<dim3(4, 256), 256>>>(nullptr, proj_w, proj_b, out);
}

// round 5
// speedup vs baseline: 1.7157x; 1.7157x over previous
#include <cuda_runtime.h>
#include <cuda_bf16.h>
#include <math.h>
#include <stdint.h>

// Problem constants
#define Bsz   8
#define Ntok  4096
#define Cch   512
#define NHh   8
#define HDd   64
#define MAXPC 321
#define EPSC  1e-6f
#define NCHK  16

// ---------------------------------------------------------------------------
// Scratch (device globals)
// ---------------------------------------------------------------------------
static __device__ float g_QQ[Bsz*NHh*Ntok*128];
static __device__ float g_KK[Bsz*NHh*Ntok*128];
static __device__ float g_G [Bsz*Ntok*Cch];
static __device__ float g_V [Bsz*Ntok*Cch];
static __device__ float g_XA[Bsz*Ntok*Cch];
static __device__ float g_VD[Bsz*Ntok*Cch];
static __device__ float g_PKV[Bsz*NHh*NCHK*128*64];
static __device__ float g_PKS[Bsz*NHh*NCHK*128];
static __device__ float g_KVC[Bsz*NHh*128*66];
static __device__ float2 g_Z [Bsz*NHh*Ntok];
static __device__ float g_scale[Cch];
static __device__ float g_power[Cch];
// bf16 hi/lo splits
static __device__ __nv_bfloat16 g_Xh [Bsz*Ntok*Cch];
static __device__ __nv_bfloat16 g_Xl [Bsz*Ntok*Cch];
static __device__ __nv_bfloat16 g_XAh[Bsz*Ntok*Cch];
static __device__ __nv_bfloat16 g_XAl[Bsz*Ntok*Cch];
static __device__ __nv_bfloat16 g_Wqgh[2*Cch*Cch];
static __device__ __nv_bfloat16 g_Wqgl[2*Cch*Cch];
static __device__ __nv_bfloat16 g_Wkvh[2*Cch*Cch];
static __device__ __nv_bfloat16 g_Wkvl[2*Cch*Cch];
static __device__ __nv_bfloat16 g_Wph [Cch*Cch];
static __device__ __nv_bfloat16 g_Wpl [Cch*Cch];

// ---------------------------------------------------------------------------
// mma.sync helpers (sm_80-compatible PTX; compiles under compute_100)
// ---------------------------------------------------------------------------
__device__ __forceinline__ uint32_t smem_u32(const void* p) {
    uint32_t a;
    asm("{ .reg .u64 t; cvta.to.shared.u64 t, %1; cvt.u32.u64 %0, t; }"
        : "=r"(a) : "l"(p));
    return a;
}
__device__ __forceinline__ void ldsm4(uint32_t* r, uint32_t addr) {
    asm volatile("ldmatrix.sync.aligned.m8n8.x4.shared.b16 {%0,%1,%2,%3}, [%4];"
        : "=r"(r[0]), "=r"(r[1]), "=r"(r[2]), "=r"(r[3]) : "r"(addr));
}
__device__ __forceinline__ void mma_bf16(float* c, const uint32_t* a,
                                         uint32_t b0, uint32_t b1) {
    asm volatile("mma.sync.aligned.m16n8k16.row.col.f32.bf16.bf16.f32 "
        "{%0,%1,%2,%3}, {%4,%5,%6,%7}, {%8,%9}, {%0,%1,%2,%3};"
        : "+f"(c[0]), "+f"(c[1]), "+f"(c[2]), "+f"(c[3])
        : "r"(a[0]), "r"(a[1]), "r"(a[2]), "r"(a[3]), "r"(b0), "r"(b1));
}

// ---------------------------------------------------------------------------
// K0: precompute softplus(scale_p), 1+4*sigmoid(power_p)
// ---------------------------------------------------------------------------
__global__ void prep_kernel(const float* __restrict__ scale_p,
                            const float* __restrict__ power_p) {
    int i = threadIdx.x;
    if (i < Cch) {
        float sp = scale_p[i];
        g_scale[i] = (sp > 20.f) ? sp : log1pf(expf(sp));
        float pp = power_p[i];
        g_power[i] = 1.0f + 4.0f / (1.0f + expf(-pp));
    }
}

// ---------------------------------------------------------------------------
// Split fp32 -> bf16 hi + bf16 lo(residual)
// ---------------------------------------------------------------------------
__global__ __launch_bounds__(256) void split_kernel(
    const float* __restrict__ src, __nv_bfloat16* __restrict__ dh,
    __nv_bfloat16* __restrict__ dl, int n4)
{
    int i = blockIdx.x * 256 + threadIdx.x;
    if (i >= n4) return;
    float4 v = ((const float4*)src)[i];
    __nv_bfloat16 h0 = __float2bfloat16(v.x), h1 = __float2bfloat16(v.y);
    __nv_bfloat16 h2 = __float2bfloat16(v.z), h3 = __float2bfloat16(v.w);
    __nv_bfloat16 l0 = __float2bfloat16(v.x - __bfloat162float(h0));
    __nv_bfloat16 l1 = __float2bfloat16(v.y - __bfloat162float(h1));
    __nv_bfloat16 l2 = __float2bfloat16(v.z - __bfloat162float(h2));
    __nv_bfloat16 l3 = __float2bfloat16(v.w - __bfloat162float(h3));
    uint2 wh, wl;
    wh.x = (uint32_t)__bfloat16_as_ushort(h0) | ((uint32_t)__bfloat16_as_ushort(h1) << 16);
    wh.y = (uint32_t)__bfloat16_as_ushort(h2) | ((uint32_t)__bfloat16_as_ushort(h3) << 16);
    wl.x = (uint32_t)__bfloat16_as_ushort(l0) | ((uint32_t)__bfloat16_as_ushort(l1) << 16);
    wl.y = (uint32_t)__bfloat16_as_ushort(l2) | ((uint32_t)__bfloat16_as_ushort(l3) << 16);
    ((uint2*)dh)[i] = wh;
    ((uint2*)dl)[i] = wl;
}

// ---------------------------------------------------------------------------
// Tensor GEMM via mma.sync: C[m][c] = sum_k A[m][k]*B[c][k], K=512,
// emulated fp32 = Ah*Bh + Ah*Bl + Al*Bh (3 bf16 MMAs).
// Block 128x128, 8 warps (2x4), warp tile 64x32, K-chunk 32.
// MODE 0: qg epilogue   MODE 1: kv (+pos_emb)   MODE 2: proj (+bias)
// ---------------------------------------------------------------------------
#define SPAD 40   // smem row stride in bf16 (80B, 16B-aligned, ldsm conflict-free)

template<int MODE>
__global__ __launch_bounds__(256) void tc_gemm(
    const __nv_bfloat16* __restrict__ Ah_g, const __nv_bfloat16* __restrict__ Al_g,
    const __nv_bfloat16* __restrict__ Bh_g, const __nv_bfloat16* __restrict__ Bl_g,
    const float* __restrict__ aux, float* __restrict__ outp)
{
    __shared__ __nv_bfloat16 sm[4][128 * SPAD];
    const int tid = threadIdx.x;
    const int wid = tid >> 5;
    const int lane = tid & 31;
    const int wm = wid >> 2;       // 0..1
    const int wn = wid & 3;        // 0..3
    const int bm = blockIdx.y * 128;
    const int bn = blockIdx.x * 128;

    float acc[4][4][4];
    #pragma unroll
    for (int i = 0; i < 4; i++)
        #pragma unroll
        for (int j = 0; j < 4; j++)
            #pragma unroll
            for (int r = 0; r < 4; r++) acc[i][j][r] = 0.f;

    const uint32_t sA_h = smem_u32(sm[0]);
    const uint32_t sA_l = smem_u32(sm[1]);
    const uint32_t sB_h = smem_u32(sm[2]);
    const uint32_t sB_l = smem_u32(sm[3]);
    // ldmatrix per-lane address pieces: rows via lane&15, k8-group via lane>>4
    const uint32_t lrow = (uint32_t)(lane & 15) * (SPAD * 2);
    const uint32_t lcol = (uint32_t)(lane >> 4) * 16;

    for (int c = 0; c < 16; c++) {
        const int k0 = c * 32;
        __syncthreads();
        #pragma unroll
        for (int mat = 0; mat < 4; mat++) {
            const __nv_bfloat16* src =
                (mat == 0) ? Ah_g : (mat == 1) ? Al_g : (mat == 2) ? Bh_g : Bl_g;
            const int rbase = (mat < 2) ? bm : bn;
            #pragma unroll
            for (int i = 0; i < 2; i++) {
                int idx = tid + i * 256;          // 0..511
                int row = idx >> 2, j = idx & 3;
                uint4 v = *(const uint4*)(src + (size_t)(rbase + row) * 512 + k0 + j * 8);
                *(uint4*)(&sm[mat][row * SPAD + j * 8]) = v;
            }
        }
        __syncthreads();

        #pragma unroll
        for (int k16 = 0; k16 < 2; k16++) {
            uint32_t ah[4][4], al[4][4], bh[2][4], bl[2][4];
            #pragma unroll
            for (int i = 0; i < 4; i++) {
                uint32_t off = (uint32_t)(wm * 64 + i * 16) * (SPAD * 2)
                             + lrow + k16 * 32 + lcol;
                ldsm4(ah[i], sA_h + off);
                ldsm4(al[i], sA_l + off);
            }
            #pragma unroll
            for (int j2 = 0; j2 < 2; j2++) {
                uint32_t off = (uint32_t)(wn * 32 + j2 * 16) * (SPAD * 2)
                             + lrow + k16 * 32 + lcol;
                ldsm4(bh[j2], sB_h + off);
                ldsm4(bl[j2], sB_l + off);
            }
            #pragma unroll
            for (int i = 0; i < 4; i++)
                #pragma unroll
                for (int j2 = 0; j2 < 2; j2++)
                    #pragma unroll
                    for (int s = 0; s < 2; s++) {
                        float* cc = acc[i][j2 * 2 + s];
                        mma_bf16(cc, ah[i], bh[j2][s], bh[j2][s + 2]);
                        mma_bf16(cc, ah[i], bl[j2][s], bl[j2][s + 2]);
                        mma_bf16(cc, al[i], bh[j2][s], bh[j2][s + 2]);
                    }
        }
    }

    // Epilogue: element (i,j,r): row = bm+wm*64+i*16+(lane>>2)+8*(r>>1)
    //                            col = bn+wn*32+j*8+(lane&3)*2+(r&1)
    const int er = lane >> 2;
    const int ec = (lane & 3) * 2;
    #pragma unroll
    for (int i = 0; i < 4; i++) {
        #pragma unroll
        for (int r2 = 0; r2 < 2; r2++) {
            const int m = bm + wm * 64 + i * 16 + er + r2 * 8;
            const int bz = m >> 12, tok = m & 4095;
            const int pemod = tok % MAXPC;
            #pragma unroll
            for (int j = 0; j < 4; j++) {
                #pragma unroll
                for (int r1 = 0; r1 < 2; r1++) {
                    const int col = bn + wn * 32 + j * 8 + ec + r1;
                    const float v0 = acc[i][j][r2 * 2 + r1];
                    if (MODE == 2) {
                        outp[(size_t)m * 512 + col] = v0 + aux[col];
                    } else if (bn < 512) {
                        float v = v0;
                        if (MODE == 1)
                            v += aux[(size_t)pemod * 512 + col];
                        v = v / g_scale[col];
                        const float p = g_power[col];
                        const float aq = fabsf(v);
                        const float rr = (aq > 0.f) ? __powf(aq, p) : 0.f;
                        const int h = col >> 6, d = col & 63;
                        float* dst = (MODE == 0 ? g_QQ : g_KK)
                                   + ((size_t)((bz * NHh + h) * Ntok + tok)) * 128 + d;
                        dst[0]  = (v > 0.f) ? rr : 0.f;
                        dst[64] = (v < 0.f) ? rr : 0.f;
                    } else {
                        float* dst = (MODE == 0 ? g_G : g_V);
                        dst[(size_t)m * 512 + (col - 512)] = v0;
                    }
                }
            }
        }
    }
}

// ---------------------------------------------------------------------------
// K3a: per (chunk, b*h) partial KV = KK^T @ Vhead + colsums
// ---------------------------------------------------------------------------
__global__ __launch_bounds__(256) void kv_partial() {
    const int chunk = blockIdx.x;
    const int bh    = blockIdx.y;
    const int b = bh >> 3, h = bh & 7;
    __shared__ float KKs[32][128];
    __shared__ float Vs[32][64];
    const int tid = threadIdx.x;
    const int d0 = (tid & 31) << 2;
    const int e0 = (tid >> 5) << 3;

    float acc[4][8];
    #pragma unroll
    for (int i = 0; i < 4; i++)
        #pragma unroll
        for (int j = 0; j < 8; j++) acc[i][j] = 0.f;
    float ks = 0.f;

    const int TPC = Ntok / NCHK;   // 256
    const float* KKb = g_KK + ((size_t)bh * Ntok + (size_t)chunk * TPC) * 128;
    const float* Vb  = g_V + ((size_t)(b * Ntok + chunk * TPC)) * Cch + h * 64;

    for (int t = 0; t < TPC / 32; t++) {
        #pragma unroll
        for (int l = 0; l < 4; l++) {
            int fidx = tid + l * 256;
            int r = fidx >> 5, d4 = (fidx & 31) << 2;
            *(float4*)&KKs[r][d4] =
                *(const float4*)(KKb + (size_t)(t * 32 + r) * 128 + d4);
        }
        #pragma unroll
        for (int l = 0; l < 2; l++) {
            int fidx = tid + l * 256;
            int r = fidx >> 4, e4 = (fidx & 15) << 2;
            *(float4*)&Vs[r][e4] =
                *(const float4*)(Vb + (size_t)(t * 32 + r) * Cch + e4);
        }
        __syncthreads();
        #pragma unroll
        for (int r = 0; r < 32; r++) {
            float4 a = *(float4*)&KKs[r][d0];
            float4 b0 = *(float4*)&Vs[r][e0];
            float4 b1 = *(float4*)&Vs[r][e0 + 4];
            float av[4] = {a.x, a.y, a.z, a.w};
            float bv[8] = {b0.x, b0.y, b0.z, b0.w, b1.x, b1.y, b1.z, b1.w};
            #pragma unroll
            for (int i = 0; i < 4; i++)
                #pragma unroll
                for (int j = 0; j < 8; j++)
                    acc[i][j] = fmaf(av[i], bv[j], acc[i][j]);
        }
        if (tid < 128) {
            float s = 0.f;
            #pragma unroll
            for (int r = 0; r < 32; r++) s += KKs[r][tid];
            ks += s;
        }
        __syncthreads();
    }

    float* P = g_PKV + ((size_t)(bh * NCHK + chunk) * 128) * 64;
    #pragma unroll
    for (int i = 0; i < 4; i++)
        #pragma unroll
        for (int j = 0; j < 8; j++)
            P[(size_t)(d0 + i) * 64 + e0 + j] = acc[i][j];
    if (tid < 128)
        g_PKS[(size_t)(bh * NCHK + chunk) * 128 + tid] = ks;
}

// ---------------------------------------------------------------------------
// K3b: reduce chunks, build KVC with opp-rotation folded in
// ---------------------------------------------------------------------------
__global__ __launch_bounds__(256) void kv_reduce() {
    const int bh = blockIdx.x;
    const int tid = threadIdx.x;
    const float inv_n = 1.0f / (float)Ntok;
    for (int p = tid; p < 128 * 64; p += 256) {
        int d = p >> 6, e = p & 63;
        int dsrc = (e < 32) ? d : ((d + 64) & 127);
        float s = 0.f;
        #pragma unroll
        for (int c2 = 0; c2 < NCHK; c2++)
            s += g_PKV[((size_t)(bh * NCHK + c2) * 128 + dsrc) * 64 + e];
        g_KVC[(size_t)bh * (128 * 66) + d * 66 + e] = s * inv_n;
    }
    if (tid < 128) {
        int d = tid, dr = (d + 64) & 127;
        float s1 = 0.f, s2 = 0.f;
        #pragma unroll
        for (int c2 = 0; c2 < NCHK; c2++) {
            s1 += g_PKS[(size_t)(bh * NCHK + c2) * 128 + d];
            s2 += g_PKS[(size_t)(bh * NCHK + c2) * 128 + dr];
        }
        g_KVC[(size_t)bh * (128 * 66) + d * 66 + 64] = s1 * inv_n;
        g_KVC[(size_t)bh * (128 * 66) + d * 66 + 65] = s2 * inv_n;
    }
}

// ---------------------------------------------------------------------------
// K4a: per-token z dots
// ---------------------------------------------------------------------------
__global__ __launch_bounds__(256) void z_kernel() {
    const int bh = blockIdx.y;
    const int tile = blockIdx.x;
    __shared__ float km[128], km2[128];
    const int tid = threadIdx.x;
    const float* __restrict__ KVCb = g_KVC + (size_t)bh * (128 * 66);
    if (tid < 128) {
        km [tid] = KVCb[tid * 66 + 64];
        km2[tid] = KVCb[tid * 66 + 65];
    }
    __syncthreads();
    const int warp = tid >> 5, lane = tid & 31;
    for (int it = 0; it < 32; it++) {
        int tok = tile * 256 + warp * 32 + it;
        float4 qv = *(const float4*)(g_QQ + ((size_t)bh * Ntok + tok) * 128 + lane * 4);
        int l4 = lane * 4;
        float p1 = qv.x*km [l4] + qv.y*km [l4+1] + qv.z*km [l4+2] + qv.w*km [l4+3];
        float p2 = qv.x*km2[l4] + qv.y*km2[l4+1] + qv.z*km2[l4+2] + qv.w*km2[l4+3];
        #pragma unroll
        for (int o = 16; o > 0; o >>= 1) {
            p1 += __shfl_down_sync(0xffffffffu, p1, o);
            p2 += __shfl_down_sync(0xffffffffu, p2, o);
        }
        if (lane == 0)
            g_Z[(size_t)bh * Ntok + tok] = make_float2(p1, p2);
    }
}

// ---------------------------------------------------------------------------
// K4: X = QQ(4096x128) @ KVC(128x64) per (b,h), /(z+eps) epilogue
// ---------------------------------------------------------------------------
__global__ __launch_bounds__(256) void attn_apply() {
    const int bh = blockIdx.y;
    const int m0 = blockIdx.x * 128;
    const int b = bh >> 3, h = bh & 7;
    __shared__ float As[128][36];
    __shared__ float Bs[32][64];
    const int tid = threadIdx.x;
    const int tm = (tid >> 4) << 3;
    const int tn = (tid & 15) << 2;

    float acc[8][4];
    #pragma unroll
    for (int i = 0; i < 8; i++)
        #pragma unroll
        for (int j = 0; j < 4; j++) acc[i][j] = 0.f;

    const float* Qb = g_QQ + ((size_t)bh * Ntok + m0) * 128;
    const float* KVCb = g_KVC + (size_t)bh * (128 * 66);

    for (int k0 = 0; k0 < 128; k0 += 32) {
        #pragma unroll
        for (int l = 0; l < 4; l++) {
            int fidx = tid + l * 256;
            int row = fidx >> 3, kc = (fidx & 7) << 2;
            *(float4*)&As[row][kc] =
                *(const float4*)(Qb + (size_t)row * 128 + k0 + kc);
        }
        #pragma unroll
        for (int l = 0; l < 8; l++) {
            int idx = tid + l * 256;
            int kk = idx >> 6, n = idx & 63;
            Bs[kk][n] = KVCb[(k0 + kk) * 66 + n];
        }
        __syncthreads();
        #pragma unroll
        for (int kk = 0; kk < 32; kk++) {
            float4 bv = *(float4*)&Bs[kk][tn];
            #pragma unroll
            for (int i = 0; i < 8; i++) {
                float a = As[tm + i][kk];
                acc[i][0] = fmaf(a, bv.x, acc[i][0]);
                acc[i][1] = fmaf(a, bv.y, acc[i][1]);
                acc[i][2] = fmaf(a, bv.z, acc[i][2]);
                acc[i][3] = fmaf(a, bv.w, acc[i][3]);
            }
        }
        __syncthreads();
    }

    #pragma unroll
    for (int i = 0; i < 8; i++) {
        int m = m0 + tm + i;
        float2 z = g_Z[(size_t)bh * Ntok + m];
        float zv = (tn < 32) ? z.x : z.y;
        float inv = 1.0f / (zv + EPSC);
        float* o = g_XA + ((size_t)(b * Ntok + m)) * Cch + h * 64 + tn;
        #pragma unroll
        for (int j = 0; j < 4; j++)
            o[j] = acc[i][j] * inv;
    }
}

// ---------------------------------------------------------------------------
// K5: depthwise 5x5 conv on the (c2, y, x2) view of v
// ---------------------------------------------------------------------------
__global__ __launch_bounds__(256) void dwconv(const float* __restrict__ Wc,
                                              const float* __restrict__ Bc) {
    const int ytile = blockIdx.x;
    const int c2 = blockIdx.y;
    const int b  = blockIdx.z;
    __shared__ float sIn[132][12];
    __shared__ float sW[25];
    __shared__ float sB;
    const int tid = threadIdx.x;
    if (tid < 25) sW[tid] = Wc[c2 * 25 + tid];
    if (tid == 25) sB = Bc[c2];
    const int y0 = ytile * 128;
    const int h = c2 >> 3;
    const int nhi = (c2 & 7) * 512;

    for (int idx = tid; idx < 132 * 12; idx += 256) {
        int sy = idx / 12, sx = idx % 12;
        int yy = y0 - 2 + sy;
        int xx = sx - 2;
        float v = 0.f;
        if (xx >= 0 && xx < 8 && yy >= 0 && yy < 4096) {
            int n = nhi + (yy >> 3);
            int d = ((yy & 7) << 3) + xx;
            v = g_V[((size_t)(b * Ntok + n)) * Cch + h * 64 + d];
        }
        sIn[sy][sx] = v;
    }
    __syncthreads();

    const int x2 = tid & 7;
    const int yl0 = tid >> 3;
    #pragma unroll
    for (int j = 0; j < 4; j++) {
        int yl = yl0 + j * 32;
        float a = sB;
        #pragma unroll
        for (int dy = 0; dy < 5; dy++)
            #pragma unroll
            for (int dx = 0; dx < 5; dx++)
                a = fmaf(sW[dy * 5 + dx], sIn[yl + dy][x2 + dx], a);
        int y = y0 + yl;
        int cc = c2 * 8 + (y >> 9);
        int nn = ((y & 511) << 3) + x2;
        g_VD[((size_t)(b * Ntok + nn)) * Cch + cc] = a;
    }
}

// ---------------------------------------------------------------------------
// K5b: XA = (XA + VD) * G, emit bf16 hi/lo split for proj GEMM
// ---------------------------------------------------------------------------
__global__ __launch_bounds__(256) void fuse_split_kernel() {
    size_t i = (size_t)blockIdx.x * 256 + threadIdx.x;
    float4 xa = ((const float4*)g_XA)[i];
    float4 vd = ((const float4*)g_VD)[i];
    float4 g  = ((const float4*)g_G)[i];
    float4 r;
    r.x = (xa.x + vd.x) * g.x;
    r.y = (xa.y + vd.y) * g.y;
    r.z = (xa.z + vd.z) * g.z;
    r.w = (xa.w + vd.w) * g.w;
    __nv_bfloat16 h0 = __float2bfloat16(r.x), h1 = __float2bfloat16(r.y);
    __nv_bfloat16 h2 = __float2bfloat16(r.z), h3 = __float2bfloat16(r.w);
    __nv_bfloat16 l0 = __float2bfloat16(r.x - __bfloat162float(h0));
    __nv_bfloat16 l1 = __float2bfloat16(r.y - __bfloat162float(h1));
    __nv_bfloat16 l2 = __float2bfloat16(r.z - __bfloat162float(h2));
    __nv_bfloat16 l3 = __float2bfloat16(r.w - __bfloat162float(h3));
    uint2 wh, wl;
    wh.x = (uint32_t)__bfloat16_as_ushort(h0) | ((uint32_t)__bfloat16_as_ushort(h1) << 16);
    wh.y = (uint32_t)__bfloat16_as_ushort(h2) | ((uint32_t)__bfloat16_as_ushort(h3) << 16);
    wl.x = (uint32_t)__bfloat16_as_ushort(l0) | ((uint32_t)__bfloat16_as_ushort(l1) << 16);
    wl.y = (uint32_t)__bfloat16_as_ushort(l2) | ((uint32_t)__bfloat16_as_ushort(l3) << 16);
    ((uint2*)g_XAh)[i] = wh;
    ((uint2*)g_XAl)[i] = wl;
}

// ---------------------------------------------------------------------------
extern "C" void kernel_launch(void* const* d_in, const int* in_sizes, int n_in,
                              void* d_out, int out_size) {
    const float* x       = (const float*)d_in[0];
    const float* qg_w    = (const float*)d_in[1];
    const float* kv_w    = (const float*)d_in[2];
    const float* proj_w  = (const float*)d_in[3];
    const float* proj_b  = (const float*)d_in[4];
    const float* power_p = (const float*)d_in[5];
    const float* scale_p = (const float*)d_in[6];
    const float* pos_emb = (const float*)d_in[7];
    const float* dwc_w   = (const float*)d_in[8];
    const float* dwc_b   = (const float*)d_in[9];
    float* out = (float*)d_out;

    __nv_bfloat16 *p_Xh, *p_Xl, *p_XAh, *p_XAl;
    __nv_bfloat16 *p_Wqgh, *p_Wqgl, *p_Wkvh, *p_Wkvl, *p_Wph, *p_Wpl;
    cudaGetSymbolAddress((void**)&p_Xh,  g_Xh);
    cudaGetSymbolAddress((void**)&p_Xl,  g_Xl);
    cudaGetSymbolAddress((void**)&p_XAh, g_XAh);
    cudaGetSymbolAddress((void**)&p_XAl, g_XAl);
    cudaGetSymbolAddress((void**)&p_Wqgh, g_Wqgh);
    cudaGetSymbolAddress((void**)&p_Wqgl, g_Wqgl);
    cudaGetSymbolAddress((void**)&p_Wkvh, g_Wkvh);
    cudaGetSymbolAddress((void**)&p_Wkvl, g_Wkvl);
    cudaGetSymbolAddress((void**)&p_Wph, g_Wph);
    cudaGetSymbolAddress((void**)&p_Wpl, g_Wpl);

    prep_kernel<<<1, 512>>>(scale_p, power_p);
    split_kernel<<<16384, 256>>>(x, p_Xh, p_Xl, Bsz * Ntok * Cch / 4);
    split_kernel<<<512, 256>>>(qg_w, p_Wqgh, p_Wqgl, 2 * Cch * Cch / 4);
    split_kernel<<<512, 256>>>(kv_w, p_Wkvh, p_Wkvl, 2 * Cch * Cch / 4);
    split_kernel<<<256, 256>>>(proj_w, p_Wph, p_Wpl, Cch * Cch / 4);

    tc_gemm<0><<<dim3(8, 256), 256>>>(p_Xh, p_Xl, p_Wqgh, p_Wqgl, nullptr, nullptr);
    tc_gemm<1><<<dim3(8, 256), 256>>>(p_Xh, p_Xl, p_Wkvh, p_Wkvl, pos_emb, nullptr);

    kv_partial<<<dim3(NCHK, 64), 256>>>();
    kv_reduce<<<64, 256>>>();
    z_kernel<<<dim3(16, 64), 256>>>();
    attn_apply<<<dim3(32, 64), 256>>>();
    dwconv<<<dim3(32, 64, 8), 256>>>(dwc_w, dwc_b);
    fuse_split_kernel<<<16384, 256>>>();

    tc_gemm<2><<<dim3(4, 256), 256>>>(p_XAh, p_XAl, p_Wph, p_Wpl, proj_b, out);
}

// round 7
// speedup vs baseline: 1.8412x; 1.0731x over previous
#include <cuda_runtime.h>
#include <cuda_bf16.h>
#include <math.h>
#include <stdint.h>

// Problem constants
#define Bsz   8
#define Ntok  4096
#define Cch   512
#define NHh   8
#define HDd   64
#define MAXPC 321
#define EPSC  1e-6f
#define NCHK  16

// ---------------------------------------------------------------------------
// Scratch (device globals)
// ---------------------------------------------------------------------------
static __device__ float g_QQ[Bsz*NHh*Ntok*128];
static __device__ float g_KK[Bsz*NHh*Ntok*128];
static __device__ float g_G [Bsz*Ntok*Cch];
static __device__ float g_V [Bsz*Ntok*Cch];
static __device__ float g_XA[Bsz*Ntok*Cch];
static __device__ float g_VD[Bsz*Ntok*Cch];
static __device__ float g_PKV[Bsz*NHh*NCHK*128*64];
static __device__ float g_PKS[Bsz*NHh*NCHK*128];
static __device__ float g_KVC[Bsz*NHh*128*66];
static __device__ float2 g_Z [Bsz*NHh*Ntok];
static __device__ float g_scale[Cch];
static __device__ float g_power[Cch];
// bf16 hi/lo splits
static __device__ __nv_bfloat16 g_Xh [Bsz*Ntok*Cch];
static __device__ __nv_bfloat16 g_Xl [Bsz*Ntok*Cch];
static __device__ __nv_bfloat16 g_XAh[Bsz*Ntok*Cch];
static __device__ __nv_bfloat16 g_XAl[Bsz*Ntok*Cch];
static __device__ __nv_bfloat16 g_Wqgh[2*Cch*Cch];
static __device__ __nv_bfloat16 g_Wqgl[2*Cch*Cch];
static __device__ __nv_bfloat16 g_Wkvh[2*Cch*Cch];
static __device__ __nv_bfloat16 g_Wkvl[2*Cch*Cch];
static __device__ __nv_bfloat16 g_Wph [Cch*Cch];
static __device__ __nv_bfloat16 g_Wpl [Cch*Cch];

// ---------------------------------------------------------------------------
// mma.sync / cp.async helpers (sm_80-compatible PTX)
// ---------------------------------------------------------------------------
__device__ __forceinline__ uint32_t smem_u32(const void* p) {
    uint32_t a;
    asm("{ .reg .u64 t; cvta.to.shared.u64 t, %1; cvt.u32.u64 %0, t; }"
        : "=r"(a) : "l"(p));
    return a;
}
__device__ __forceinline__ void ldsm4(uint32_t* r, uint32_t addr) {
    asm volatile("ldmatrix.sync.aligned.m8n8.x4.shared.b16 {%0,%1,%2,%3}, [%4];"
        : "=r"(r[0]), "=r"(r[1]), "=r"(r[2]), "=r"(r[3]) : "r"(addr));
}
__device__ __forceinline__ void mma_bf16(float* c, const uint32_t* a,
                                         uint32_t b0, uint32_t b1) {
    asm volatile("mma.sync.aligned.m16n8k16.row.col.f32.bf16.bf16.f32 "
        "{%0,%1,%2,%3}, {%4,%5,%6,%7}, {%8,%9}, {%0,%1,%2,%3};"
        : "+f"(c[0]), "+f"(c[1]), "+f"(c[2]), "+f"(c[3])
        : "r"(a[0]), "r"(a[1]), "r"(a[2]), "r"(a[3]), "r"(b0), "r"(b1));
}
__device__ __forceinline__ void cp_async16(uint32_t daddr, const void* gptr) {
    asm volatile("cp.async.cg.shared.global [%0], [%1], 16;"
                 :: "r"(daddr), "l"(gptr) : "memory");
}
#define CP_COMMIT() asm volatile("cp.async.commit_group;" ::: "memory")
#define CP_WAIT(N)  asm volatile("cp.async.wait_group %0;" :: "n"(N) : "memory")

// ---------------------------------------------------------------------------
// K0: precompute softplus(scale_p), 1+4*sigmoid(power_p)
// ---------------------------------------------------------------------------
__global__ void prep_kernel(const float* __restrict__ scale_p,
                            const float* __restrict__ power_p) {
    int i = threadIdx.x;
    if (i < Cch) {
        float sp = scale_p[i];
        g_scale[i] = (sp > 20.f) ? sp : log1pf(expf(sp));
        float pp = power_p[i];
        g_power[i] = 1.0f + 4.0f / (1.0f + expf(-pp));
    }
}

// ---------------------------------------------------------------------------
// Split fp32 -> bf16 hi + bf16 lo(residual)
// ---------------------------------------------------------------------------
__global__ __launch_bounds__(256) void split_kernel(
    const float* __restrict__ src, __nv_bfloat16* __restrict__ dh,
    __nv_bfloat16* __restrict__ dl, int n4)
{
    int i = blockIdx.x * 256 + threadIdx.x;
    if (i >= n4) return;
    float4 v = ((const float4*)src)[i];
    __nv_bfloat16 h0 = __float2bfloat16(v.x), h1 = __float2bfloat16(v.y);
    __nv_bfloat16 h2 = __float2bfloat16(v.z), h3 = __float2bfloat16(v.w);
    __nv_bfloat16 l0 = __float2bfloat16(v.x - __bfloat162float(h0));
    __nv_bfloat16 l1 = __float2bfloat16(v.y - __bfloat162float(h1));
    __nv_bfloat16 l2 = __float2bfloat16(v.z - __bfloat162float(h2));
    __nv_bfloat16 l3 = __float2bfloat16(v.w - __bfloat162float(h3));
    uint2 wh, wl;
    wh.x = (uint32_t)__bfloat16_as_ushort(h0) | ((uint32_t)__bfloat16_as_ushort(h1) << 16);
    wh.y = (uint32_t)__bfloat16_as_ushort(h2) | ((uint32_t)__bfloat16_as_ushort(h3) << 16);
    wl.x = (uint32_t)__bfloat16_as_ushort(l0) | ((uint32_t)__bfloat16_as_ushort(l1) << 16);
    wl.y = (uint32_t)__bfloat16_as_ushort(l2) | ((uint32_t)__bfloat16_as_ushort(l3) << 16);
    ((uint2*)dh)[i] = wh;
    ((uint2*)dl)[i] = wl;
}

// ---------------------------------------------------------------------------
// Tensor GEMM via mma.sync + cp.async double buffering.
// C[m][c] = sum_k A[m][k]*B[c][k], K=512, emulated fp32 (3 bf16 MMAs).
// Block 128x128, 8 warps (2x4), warp tile 64x32, K-chunk 32, 2 stages.
// ---------------------------------------------------------------------------
#define SPAD 40                          // smem row stride in bf16 (80B)
#define MATB (128 * SPAD * 2)            // 10240 B per matrix tile
#define STAGEB (4 * MATB)                // 40960 B per stage
#define TCSMEM (2 * STAGEB)              // 81920 B total

template<int MODE>
__global__ __launch_bounds__(256) void tc_gemm(
    const __nv_bfloat16* __restrict__ Ah_g, const __nv_bfloat16* __restrict__ Al_g,
    const __nv_bfloat16* __restrict__ Bh_g, const __nv_bfloat16* __restrict__ Bl_g,
    const float* __restrict__ aux, float* __restrict__ outp)
{
    extern __shared__ __nv_bfloat16 dsm[];
    const uint32_t sbase = smem_u32(dsm);
    const int tid = threadIdx.x;
    const int wid = tid >> 5;
    const int lane = tid & 31;
    const int wm = wid >> 2;
    const int wn = wid & 3;
    const int bm = blockIdx.y * 128;
    const int bn = blockIdx.x * 128;

    float acc[4][4][4];
    #pragma unroll
    for (int i = 0; i < 4; i++)
        #pragma unroll
        for (int j = 0; j < 4; j++)
            #pragma unroll
            for (int r = 0; r < 4; r++) acc[i][j][r] = 0.f;

    // per-thread load coords (2 x 16B per matrix per chunk)
    const int lrow0 = tid >> 2, lj0 = tid & 3;            // idx 0..255
    const int lrow1 = (tid + 256) >> 2, lj1 = tid & 3;    // idx 256..511
    const uint32_t lrowa = (uint32_t)(lane & 15) * (SPAD * 2);
    const uint32_t lcola = (uint32_t)(lane >> 4) * 16;

    const __nv_bfloat16* srcs[4] = {Ah_g, Al_g, Bh_g, Bl_g};

    // prefetch chunk 0 into stage 0
    {
        const int k0 = 0;
        #pragma unroll
        for (int mat = 0; mat < 4; mat++) {
            const int rbase = (mat < 2) ? bm : bn;
            cp_async16(sbase + mat * MATB + (uint32_t)(lrow0 * 80 + lj0 * 16),
                       srcs[mat] + (size_t)(rbase + lrow0) * 512 + k0 + lj0 * 8);
            cp_async16(sbase + mat * MATB + (uint32_t)(lrow1 * 80 + lj1 * 16),
                       srcs[mat] + (size_t)(rbase + lrow1) * 512 + k0 + lj1 * 8);
        }
        CP_COMMIT();
    }

    for (int c = 0; c < 16; c++) {
        const int stage = c & 1;
        if (c + 1 < 16) {
            const int k0 = (c + 1) * 32;
            const uint32_t sb2 = sbase + (uint32_t)((c + 1) & 1) * STAGEB;
            #pragma unroll
            for (int mat = 0; mat < 4; mat++) {
                const int rbase = (mat < 2) ? bm : bn;
                cp_async16(sb2 + mat * MATB + (uint32_t)(lrow0 * 80 + lj0 * 16),
                           srcs[mat] + (size_t)(rbase + lrow0) * 512 + k0 + lj0 * 8);
                cp_async16(sb2 + mat * MATB + (uint32_t)(lrow1 * 80 + lj1 * 16),
                           srcs[mat] + (size_t)(rbase + lrow1) * 512 + k0 + lj1 * 8);
            }
            CP_COMMIT();
            CP_WAIT(1);
        } else {
            CP_WAIT(0);
        }
        __syncthreads();

        const uint32_t sA_h = sbase + (uint32_t)stage * STAGEB;
        const uint32_t sA_l = sA_h + MATB;
        const uint32_t sB_h = sA_h + 2 * MATB;
        const uint32_t sB_l = sA_h + 3 * MATB;

        #pragma unroll
        for (int k16 = 0; k16 < 2; k16++) {
            uint32_t ah[4][4], al[4][4], bh[2][4], bl[2][4];
            #pragma unroll
            for (int i = 0; i < 4; i++) {
                uint32_t off = (uint32_t)(wm * 64 + i * 16) * (SPAD * 2)
                             + lrowa + k16 * 32 + lcola;
                ldsm4(ah[i], sA_h + off);
                ldsm4(al[i], sA_l + off);
            }
            #pragma unroll
            for (int j2 = 0; j2 < 2; j2++) {
                uint32_t off = (uint32_t)(wn * 32 + j2 * 16) * (SPAD * 2)
                             + lrowa + k16 * 32 + lcola;
                ldsm4(bh[j2], sB_h + off);
                ldsm4(bl[j2], sB_l + off);
            }
            #pragma unroll
            for (int i = 0; i < 4; i++)
                #pragma unroll
                for (int j2 = 0; j2 < 2; j2++)
                    #pragma unroll
                    for (int s = 0; s < 2; s++) {
                        float* cc = acc[i][j2 * 2 + s];
                        mma_bf16(cc, ah[i], bh[j2][s], bh[j2][s + 2]);
                        mma_bf16(cc, ah[i], bl[j2][s], bl[j2][s + 2]);
                        mma_bf16(cc, al[i], bh[j2][s], bh[j2][s + 2]);
                    }
        }
        __syncthreads();
    }

    // Epilogue
    const int er = lane >> 2;
    const int ec = (lane & 3) * 2;
    #pragma unroll
    for (int i = 0; i < 4; i++) {
        #pragma unroll
        for (int r2 = 0; r2 < 2; r2++) {
            const int m = bm + wm * 64 + i * 16 + er + r2 * 8;
            const int bz = m >> 12, tok = m & 4095;
            const int pemod = tok % MAXPC;
            #pragma unroll
            for (int j = 0; j < 4; j++) {
                #pragma unroll
                for (int r1 = 0; r1 < 2; r1++) {
                    const int col = bn + wn * 32 + j * 8 + ec + r1;
                    const float v0 = acc[i][j][r2 * 2 + r1];
                    if (MODE == 2) {
                        outp[(size_t)m * 512 + col] = v0 + aux[col];
                    } else if (bn < 512) {
                        float v = v0;
                        if (MODE == 1)
                            v += aux[(size_t)pemod * 512 + col];
                        v = v / g_scale[col];
                        const float p = g_power[col];
                        const float aq = fabsf(v);
                        const float rr = (aq > 0.f) ? __powf(aq, p) : 0.f;
                        const int h = col >> 6, d = col & 63;
                        float* dst = (MODE == 0 ? g_QQ : g_KK)
                                   + ((size_t)((bz * NHh + h) * Ntok + tok)) * 128 + d;
                        dst[0]  = (v > 0.f) ? rr : 0.f;
                        dst[64] = (v < 0.f) ? rr : 0.f;
                    } else {
                        float* dst = (MODE == 0 ? g_G : g_V);
                        dst[(size_t)m * 512 + (col - 512)] = v0;
                    }
                }
            }
        }
    }
}

// ---------------------------------------------------------------------------
// K3a: per (chunk, b*h) partial KV = KK^T @ Vhead + colsums
// ---------------------------------------------------------------------------
__global__ __launch_bounds__(256) void kv_partial() {
    const int chunk = blockIdx.x;
    const int bh    = blockIdx.y;
    const int b = bh >> 3, h = bh & 7;
    __shared__ float KKs[32][128];
    __shared__ float Vs[32][64];
    const int tid = threadIdx.x;
    const int d0 = (tid & 31) << 2;
    const int e0 = (tid >> 5) << 3;

    float acc[4][8];
    #pragma unroll
    for (int i = 0; i < 4; i++)
        #pragma unroll
        for (int j = 0; j < 8; j++) acc[i][j] = 0.f;
    float ks = 0.f;

    const int TPC = Ntok / NCHK;
    const float* KKb = g_KK + ((size_t)bh * Ntok + (size_t)chunk * TPC) * 128;
    const float* Vb  = g_V + ((size_t)(b * Ntok + chunk * TPC)) * Cch + h * 64;

    for (int t = 0; t < TPC / 32; t++) {
        #pragma unroll
        for (int l = 0; l < 4; l++) {
            int fidx = tid + l * 256;
            int r = fidx >> 5, d4 = (fidx & 31) << 2;
            *(float4*)&KKs[r][d4] =
                *(const float4*)(KKb + (size_t)(t * 32 + r) * 128 + d4);
        }
        #pragma unroll
        for (int l = 0; l < 2; l++) {
            int fidx = tid + l * 256;
            int r = fidx >> 4, e4 = (fidx & 15) << 2;
            *(float4*)&Vs[r][e4] =
                *(const float4*)(Vb + (size_t)(t * 32 + r) * Cch + e4);
        }
        __syncthreads();
        #pragma unroll
        for (int r = 0; r < 32; r++) {
            float4 a = *(float4*)&KKs[r][d0];
            float4 b0 = *(float4*)&Vs[r][e0];
            float4 b1 = *(float4*)&Vs[r][e0 + 4];
            float av[4] = {a.x, a.y, a.z, a.w};
            float bv[8] = {b0.x, b0.y, b0.z, b0.w, b1.x, b1.y, b1.z, b1.w};
            #pragma unroll
            for (int i = 0; i < 4; i++)
                #pragma unroll
                for (int j = 0; j < 8; j++)
                    acc[i][j] = fmaf(av[i], bv[j], acc[i][j]);
        }
        if (tid < 128) {
            float s = 0.f;
            #pragma unroll
            for (int r = 0; r < 32; r++) s += KKs[r][tid];
            ks += s;
        }
        __syncthreads();
    }

    float* P = g_PKV + ((size_t)(bh * NCHK + chunk) * 128) * 64;
    #pragma unroll
    for (int i = 0; i < 4; i++)
        #pragma unroll
        for (int j = 0; j < 8; j++)
            P[(size_t)(d0 + i) * 64 + e0 + j] = acc[i][j];
    if (tid < 128)
        g_PKS[(size_t)(bh * NCHK + chunk) * 128 + tid] = ks;
}

// ---------------------------------------------------------------------------
// K3b: reduce chunks, build KVC with opp-rotation folded in
// ---------------------------------------------------------------------------
__global__ __launch_bounds__(256) void kv_reduce() {
    const int bh = blockIdx.x;
    const int tid = threadIdx.x;
    const float inv_n = 1.0f / (float)Ntok;
    for (int p = tid; p < 128 * 64; p += 256) {
        int d = p >> 6, e = p & 63;
        int dsrc = (e < 32) ? d : ((d + 64) & 127);
        float s = 0.f;
        #pragma unroll
        for (int c2 = 0; c2 < NCHK; c2++)
            s += g_PKV[((size_t)(bh * NCHK + c2) * 128 + dsrc) * 64 + e];
        g_KVC[(size_t)bh * (128 * 66) + d * 66 + e] = s * inv_n;
    }
    if (tid < 128) {
        int d = tid, dr = (d + 64) & 127;
        float s1 = 0.f, s2 = 0.f;
        #pragma unroll
        for (int c2 = 0; c2 < NCHK; c2++) {
            s1 += g_PKS[(size_t)(bh * NCHK + c2) * 128 + d];
            s2 += g_PKS[(size_t)(bh * NCHK + c2) * 128 + dr];
        }
        g_KVC[(size_t)bh * (128 * 66) + d * 66 + 64] = s1 * inv_n;
        g_KVC[(size_t)bh * (128 * 66) + d * 66 + 65] = s2 * inv_n;
    }
}

// ---------------------------------------------------------------------------
// K4a: per-token z dots
// ---------------------------------------------------------------------------
__global__ __launch_bounds__(256) void z_kernel() {
    const int bh = blockIdx.y;
    const int tile = blockIdx.x;
    __shared__ float km[128], km2[128];
    const int tid = threadIdx.x;
    const float* __restrict__ KVCb = g_KVC + (size_t)bh * (128 * 66);
    if (tid < 128) {
        km [tid] = KVCb[tid * 66 + 64];
        km2[tid] = KVCb[tid * 66 + 65];
    }
    __syncthreads();
    const int warp = tid >> 5, lane = tid & 31;
    for (int it = 0; it < 32; it++) {
        int tok = tile * 256 + warp * 32 + it;
        float4 qv = *(const float4*)(g_QQ + ((size_t)bh * Ntok + tok) * 128 + lane * 4);
        int l4 = lane * 4;
        float p1 = qv.x*km [l4] + qv.y*km [l4+1] + qv.z*km [l4+2] + qv.w*km [l4+3];
        float p2 = qv.x*km2[l4] + qv.y*km2[l4+1] + qv.z*km2[l4+2] + qv.w*km2[l4+3];
        #pragma unroll
        for (int o = 16; o > 0; o >>= 1) {
            p1 += __shfl_down_sync(0xffffffffu, p1, o);
            p2 += __shfl_down_sync(0xffffffffu, p2, o);
        }
        if (lane == 0)
            g_Z[(size_t)bh * Ntok + tok] = make_float2(p1, p2);
    }
}

// ---------------------------------------------------------------------------
// K4: X = QQ(4096x128) @ KVC(128x64) per (b,h), /(z+eps) epilogue
// ---------------------------------------------------------------------------
__global__ __launch_bounds__(256) void attn_apply() {
    const int bh = blockIdx.y;
    const int m0 = blockIdx.x * 128;
    const int b = bh >> 3, h = bh & 7;
    __shared__ float As[128][36];
    __shared__ float Bs[32][64];
    const int tid = threadIdx.x;
    const int tm = (tid >> 4) << 3;
    const int tn = (tid & 15) << 2;

    float acc[8][4];
    #pragma unroll
    for (int i = 0; i < 8; i++)
        #pragma unroll
        for (int j = 0; j < 4; j++) acc[i][j] = 0.f;

    const float* Qb = g_QQ + ((size_t)bh * Ntok + m0) * 128;
    const float* KVCb = g_KVC + (size_t)bh * (128 * 66);

    for (int k0 = 0; k0 < 128; k0 += 32) {
        #pragma unroll
        for (int l = 0; l < 4; l++) {
            int fidx = tid + l * 256;
            int row = fidx >> 3, kc = (fidx & 7) << 2;
            *(float4*)&As[row][kc] =
                *(const float4*)(Qb + (size_t)row * 128 + k0 + kc);
        }
        #pragma unroll
        for (int l = 0; l < 8; l++) {
            int idx = tid + l * 256;
            int kk = idx >> 6, n = idx & 63;
            Bs[kk][n] = KVCb[(k0 + kk) * 66 + n];
        }
        __syncthreads();
        #pragma unroll
        for (int kk = 0; kk < 32; kk++) {
            float4 bv = *(float4*)&Bs[kk][tn];
            #pragma unroll
            for (int i = 0; i < 8; i++) {
                float a = As[tm + i][kk];
                acc[i][0] = fmaf(a, bv.x, acc[i][0]);
                acc[i][1] = fmaf(a, bv.y, acc[i][1]);
                acc[i][2] = fmaf(a, bv.z, acc[i][2]);
                acc[i][3] = fmaf(a, bv.w, acc[i][3]);
            }
        }
        __syncthreads();
    }

    #pragma unroll
    for (int i = 0; i < 8; i++) {
        int m = m0 + tm + i;
        float2 z = g_Z[(size_t)bh * Ntok + m];
        float zv = (tn < 32) ? z.x : z.y;
        float inv = 1.0f / (zv + EPSC);
        float* o = g_XA + ((size_t)(b * Ntok + m)) * Cch + h * 64 + tn;
        #pragma unroll
        for (int j = 0; j < 4; j++)
            o[j] = acc[i][j] * inv;
    }
}

// ---------------------------------------------------------------------------
// K5: depthwise 5x5 conv on the (c2, y, x2) view of v
// ---------------------------------------------------------------------------
__global__ __launch_bounds__(256) void dwconv(const float* __restrict__ Wc,
                                              const float* __restrict__ Bc) {
    const int ytile = blockIdx.x;
    const int c2 = blockIdx.y;
    const int b  = blockIdx.z;
    __shared__ float sIn[132][12];
    __shared__ float sW[25];
    __shared__ float sB;
    const int tid = threadIdx.x;
    if (tid < 25) sW[tid] = Wc[c2 * 25 + tid];
    if (tid == 25) sB = Bc[c2];
    const int y0 = ytile * 128;
    const int h = c2 >> 3;
    const int nhi = (c2 & 7) * 512;

    for (int idx = tid; idx < 132 * 12; idx += 256) {
        int sy = idx / 12, sx = idx % 12;
        int yy = y0 - 2 + sy;
        int xx = sx - 2;
        float v = 0.f;
        if (xx >= 0 && xx < 8 && yy >= 0 && yy < 4096) {
            int n = nhi + (yy >> 3);
            int d = ((yy & 7) << 3) + xx;
            v = g_V[((size_t)(b * Ntok + n)) * Cch + h * 64 + d];
        }
        sIn[sy][sx] = v;
    }
    __syncthreads();

    const int x2 = tid & 7;
    const int yl0 = tid >> 3;
    #pragma unroll
    for (int j = 0; j < 4; j++) {
        int yl = yl0 + j * 32;
        float a = sB;
        #pragma unroll
        for (int dy = 0; dy < 5; dy++)
            #pragma unroll
            for (int dx = 0; dx < 5; dx++)
                a = fmaf(sW[dy * 5 + dx], sIn[yl + dy][x2 + dx], a);
        int y = y0 + yl;
        int cc = c2 * 8 + (y >> 9);
        int nn = ((y & 511) << 3) + x2;
        g_VD[((size_t)(b * Ntok + nn)) * Cch + cc] = a;
    }
}

// ---------------------------------------------------------------------------
// K5b: XA = (XA + VD) * G, emit bf16 hi/lo split for proj GEMM
// ---------------------------------------------------------------------------
__global__ __launch_bounds__(256) void fuse_split_kernel() {
    size_t i = (size_t)blockIdx.x * 256 + threadIdx.x;
    float4 xa = ((const float4*)g_XA)[i];
    float4 vd = ((const float4*)g_VD)[i];
    float4 g  = ((const float4*)g_G)[i];
    float4 r;
    r.x = (xa.x + vd.x) * g.x;
    r.y = (xa.y + vd.y) * g.y;
    r.z = (xa.z + vd.z) * g.z;
    r.w = (xa.w + vd.w) * g.w;
    __nv_bfloat16 h0 = __float2bfloat16(r.x), h1 = __float2bfloat16(r.y);
    __nv_bfloat16 h2 = __float2bfloat16(r.z), h3 = __float2bfloat16(r.w);
    __nv_bfloat16 l0 = __float2bfloat16(r.x - __bfloat162float(h0));
    __nv_bfloat16 l1 = __float2bfloat16(r.y - __bfloat162float(h1));
    __nv_bfloat16 l2 = __float2bfloat16(r.z - __bfloat162float(h2));
    __nv_bfloat16 l3 = __float2bfloat16(r.w - __bfloat162float(h3));
    uint2 wh, wl;
    wh.x = (uint32_t)__bfloat16_as_ushort(h0) | ((uint32_t)__bfloat16_as_ushort(h1) << 16);
    wh.y = (uint32_t)__bfloat16_as_ushort(h2) | ((uint32_t)__bfloat16_as_ushort(h3) << 16);
    wl.x = (uint32_t)__bfloat16_as_ushort(l0) | ((uint32_t)__bfloat16_as_ushort(l1) << 16);
    wl.y = (uint32_t)__bfloat16_as_ushort(l2) | ((uint32_t)__bfloat16_as_ushort(l3) << 16);
    ((uint2*)g_XAh)[i] = wh;
    ((uint2*)g_XAl)[i] = wl;
}

// ---------------------------------------------------------------------------
extern "C" void kernel_launch(void* const* d_in, const int* in_sizes, int n_in,
                              void* d_out, int out_size) {
    const float* x       = (const float*)d_in[0];
    const float* qg_w    = (const float*)d_in[1];
    const float* kv_w    = (const float*)d_in[2];
    const float* proj_w  = (const float*)d_in[3];
    const float* proj_b  = (const float*)d_in[4];
    const float* power_p = (const float*)d_in[5];
    const float* scale_p = (const float*)d_in[6];
    const float* pos_emb = (const float*)d_in[7];
    const float* dwc_w   = (const float*)d_in[8];
    const float* dwc_b   = (const float*)d_in[9];
    float* out = (float*)d_out;

    __nv_bfloat16 *p_Xh, *p_Xl, *p_XAh, *p_XAl;
    __nv_bfloat16 *p_Wqgh, *p_Wqgl, *p_Wkvh, *p_Wkvl, *p_Wph, *p_Wpl;
    cudaGetSymbolAddress((void**)&p_Xh,  g_Xh);
    cudaGetSymbolAddress((void**)&p_Xl,  g_Xl);
    cudaGetSymbolAddress((void**)&p_XAh, g_XAh);
    cudaGetSymbolAddress((void**)&p_XAl, g_XAl);
    cudaGetSymbolAddress((void**)&p_Wqgh, g_Wqgh);
    cudaGetSymbolAddress((void**)&p_Wqgl, g_Wqgl);
    cudaGetSymbolAddress((void**)&p_Wkvh, g_Wkvh);
    cudaGetSymbolAddress((void**)&p_Wkvl, g_Wkvl);
    cudaGetSymbolAddress((void**)&p_Wph, g_Wph);
    cudaGetSymbolAddress((void**)&p_Wpl, g_Wpl);

    cudaFuncSetAttribute(tc_gemm<0>, cudaFuncAttributeMaxDynamicSharedMemorySize, TCSMEM);
    cudaFuncSetAttribute(tc_gemm<1>, cudaFuncAttributeMaxDynamicSharedMemorySize, TCSMEM);
    cudaFuncSetAttribute(tc_gemm<2>, cudaFuncAttributeMaxDynamicSharedMemorySize, TCSMEM);

    prep_kernel<<<1, 512>>>(scale_p, power_p);
    split_kernel<<<16384, 256>>>(x, p_Xh, p_Xl, Bsz * Ntok * Cch / 4);
    split_kernel<<<512, 256>>>(qg_w, p_Wqgh, p_Wqgl, 2 * Cch * Cch / 4);
    split_kernel<<<512, 256>>>(kv_w, p_Wkvh, p_Wkvl, 2 * Cch * Cch / 4);
    split_kernel<<<256, 256>>>(proj_w, p_Wph, p_Wpl, Cch * Cch / 4);

    tc_gemm<0><<<dim3(8, 256), 256, TCSMEM>>>(p_Xh, p_Xl, p_Wqgh, p_Wqgl, nullptr, nullptr);
    tc_gemm<1><<<dim3(8, 256), 256, TCSMEM>>>(p_Xh, p_Xl, p_Wkvh, p_Wkvl, pos_emb, nullptr);

    kv_partial<<<dim3(NCHK, 64), 256>>>();
    kv_reduce<<<64, 256>>>();
    z_kernel<<<dim3(16, 64), 256>>>();
    attn_apply<<<dim3(32, 64), 256>>>();
    dwconv<<<dim3(32, 64, 8), 256>>>(dwc_w, dwc_b);
    fuse_split_kernel<<<16384, 256>>>();

    tc_gemm<2><<<dim3(4, 256), 256, TCSMEM>>>(p_XAh, p_XAl, p_Wph, p_Wpl, proj_b, out);
}

// round 8
// speedup vs baseline: 1.9297x; 1.0480x over previous
#include <cuda_runtime.h>
#include <cuda_bf16.h>
#include <math.h>
#include <stdint.h>

// Problem constants
#define Bsz   8
#define Ntok  4096
#define Cch   512
#define NHh   8
#define HDd   64
#define MAXPC 321
#define EPSC  1e-6f
#define NCHK  16

// ---------------------------------------------------------------------------
// Scratch (device globals)
// ---------------------------------------------------------------------------
static __device__ float g_QQc[Bsz*NHh*Ntok*64];   // compact signed |q|^p
static __device__ float g_KKc[Bsz*NHh*Ntok*64];   // compact signed |k|^p
static __device__ float g_G [Bsz*Ntok*Cch];
static __device__ float g_V [Bsz*Ntok*Cch];
static __device__ float g_VD[Bsz*Ntok*Cch];
static __device__ float g_PKV[Bsz*NHh*NCHK*128*64];
static __device__ float g_PKS[Bsz*NHh*NCHK*128];
static __device__ float g_KVC[Bsz*NHh*128*66];
static __device__ float2 g_Z [Bsz*NHh*Ntok];
static __device__ float g_scale[Cch];
static __device__ float g_power[Cch];
// bf16 hi/lo splits
static __device__ __nv_bfloat16 g_Xh [Bsz*Ntok*Cch];
static __device__ __nv_bfloat16 g_Xl [Bsz*Ntok*Cch];
static __device__ __nv_bfloat16 g_XAh[Bsz*Ntok*Cch];
static __device__ __nv_bfloat16 g_XAl[Bsz*Ntok*Cch];
static __device__ __nv_bfloat16 g_Wqgh[2*Cch*Cch];
static __device__ __nv_bfloat16 g_Wqgl[2*Cch*Cch];
static __device__ __nv_bfloat16 g_Wkvh[2*Cch*Cch];
static __device__ __nv_bfloat16 g_Wkvl[2*Cch*Cch];
static __device__ __nv_bfloat16 g_Wph [Cch*Cch];
static __device__ __nv_bfloat16 g_Wpl [Cch*Cch];

// ---------------------------------------------------------------------------
// mma.sync / cp.async helpers (sm_80-compatible PTX)
// ---------------------------------------------------------------------------
__device__ __forceinline__ uint32_t smem_u32(const void* p) {
    uint32_t a;
    asm("{ .reg .u64 t; cvta.to.shared.u64 t, %1; cvt.u32.u64 %0, t; }"
        : "=r"(a) : "l"(p));
    return a;
}
__device__ __forceinline__ void ldsm4(uint32_t* r, uint32_t addr) {
    asm volatile("ldmatrix.sync.aligned.m8n8.x4.shared.b16 {%0,%1,%2,%3}, [%4];"
        : "=r"(r[0]), "=r"(r[1]), "=r"(r[2]), "=r"(r[3]) : "r"(addr));
}
__device__ __forceinline__ void mma_bf16(float* c, const uint32_t* a,
                                         uint32_t b0, uint32_t b1) {
    asm volatile("mma.sync.aligned.m16n8k16.row.col.f32.bf16.bf16.f32 "
        "{%0,%1,%2,%3}, {%4,%5,%6,%7}, {%8,%9}, {%0,%1,%2,%3};"
        : "+f"(c[0]), "+f"(c[1]), "+f"(c[2]), "+f"(c[3])
        : "r"(a[0]), "r"(a[1]), "r"(a[2]), "r"(a[3]), "r"(b0), "r"(b1));
}
__device__ __forceinline__ void cp_async16(uint32_t daddr, const void* gptr) {
    asm volatile("cp.async.cg.shared.global [%0], [%1], 16;"
                 :: "r"(daddr), "l"(gptr) : "memory");
}
#define CP_COMMIT() asm volatile("cp.async.commit_group;" ::: "memory")
#define CP_WAIT(N)  asm volatile("cp.async.wait_group %0;" :: "n"(N) : "memory")

// ---------------------------------------------------------------------------
// K0: precompute softplus(scale_p), 1+4*sigmoid(power_p)
// ---------------------------------------------------------------------------
__global__ void prep_kernel(const float* __restrict__ scale_p,
                            const float* __restrict__ power_p) {
    int i = threadIdx.x;
    if (i < Cch) {
        float sp = scale_p[i];
        g_scale[i] = (sp > 20.f) ? sp : log1pf(expf(sp));
        float pp = power_p[i];
        g_power[i] = 1.0f + 4.0f / (1.0f + expf(-pp));
    }
}

// ---------------------------------------------------------------------------
// Split fp32 -> bf16 hi + bf16 lo(residual)
// ---------------------------------------------------------------------------
__global__ __launch_bounds__(256) void split_kernel(
    const float* __restrict__ src, __nv_bfloat16* __restrict__ dh,
    __nv_bfloat16* __restrict__ dl, int n4)
{
    int i = blockIdx.x * 256 + threadIdx.x;
    if (i >= n4) return;
    float4 v = ((const float4*)src)[i];
    __nv_bfloat16 h0 = __float2bfloat16(v.x), h1 = __float2bfloat16(v.y);
    __nv_bfloat16 h2 = __float2bfloat16(v.z), h3 = __float2bfloat16(v.w);
    __nv_bfloat16 l0 = __float2bfloat16(v.x - __bfloat162float(h0));
    __nv_bfloat16 l1 = __float2bfloat16(v.y - __bfloat162float(h1));
    __nv_bfloat16 l2 = __float2bfloat16(v.z - __bfloat162float(h2));
    __nv_bfloat16 l3 = __float2bfloat16(v.w - __bfloat162float(h3));
    uint2 wh, wl;
    wh.x = (uint32_t)__bfloat16_as_ushort(h0) | ((uint32_t)__bfloat16_as_ushort(h1) << 16);
    wh.y = (uint32_t)__bfloat16_as_ushort(h2) | ((uint32_t)__bfloat16_as_ushort(h3) << 16);
    wl.x = (uint32_t)__bfloat16_as_ushort(l0) | ((uint32_t)__bfloat16_as_ushort(l1) << 16);
    wl.y = (uint32_t)__bfloat16_as_ushort(l2) | ((uint32_t)__bfloat16_as_ushort(l3) << 16);
    ((uint2*)dh)[i] = wh;
    ((uint2*)dl)[i] = wl;
}

// ---------------------------------------------------------------------------
// Tensor GEMM via mma.sync + cp.async double buffering. (mainloop unchanged)
// MODE 0: qg (compact signed QQc + G)   MODE 1: kv (compact KKc + V)
// MODE 2: proj (+bias)
// ---------------------------------------------------------------------------
#define SPAD 40
#define MATB (128 * SPAD * 2)
#define STAGEB (4 * MATB)
#define TCSMEM (2 * STAGEB)

template<int MODE>
__global__ __launch_bounds__(256) void tc_gemm(
    const __nv_bfloat16* __restrict__ Ah_g, const __nv_bfloat16* __restrict__ Al_g,
    const __nv_bfloat16* __restrict__ Bh_g, const __nv_bfloat16* __restrict__ Bl_g,
    const float* __restrict__ aux, float* __restrict__ outp)
{
    extern __shared__ __nv_bfloat16 dsm[];
    const uint32_t sbase = smem_u32(dsm);
    const int tid = threadIdx.x;
    const int wid = tid >> 5;
    const int lane = tid & 31;
    const int wm = wid >> 2;
    const int wn = wid & 3;
    const int bm = blockIdx.y * 128;
    const int bn = blockIdx.x * 128;

    float acc[4][4][4];
    #pragma unroll
    for (int i = 0; i < 4; i++)
        #pragma unroll
        for (int j = 0; j < 4; j++)
            #pragma unroll
            for (int r = 0; r < 4; r++) acc[i][j][r] = 0.f;

    const int lrow0 = tid >> 2, lj0 = tid & 3;
    const int lrow1 = (tid + 256) >> 2, lj1 = tid & 3;
    const uint32_t lrowa = (uint32_t)(lane & 15) * (SPAD * 2);
    const uint32_t lcola = (uint32_t)(lane >> 4) * 16;

    const __nv_bfloat16* srcs[4] = {Ah_g, Al_g, Bh_g, Bl_g};

    {
        const int k0 = 0;
        #pragma unroll
        for (int mat = 0; mat < 4; mat++) {
            const int rbase = (mat < 2) ? bm : bn;
            cp_async16(sbase + mat * MATB + (uint32_t)(lrow0 * 80 + lj0 * 16),
                       srcs[mat] + (size_t)(rbase + lrow0) * 512 + k0 + lj0 * 8);
            cp_async16(sbase + mat * MATB + (uint32_t)(lrow1 * 80 + lj1 * 16),
                       srcs[mat] + (size_t)(rbase + lrow1) * 512 + k0 + lj1 * 8);
        }
        CP_COMMIT();
    }

    for (int c = 0; c < 16; c++) {
        const int stage = c & 1;
        if (c + 1 < 16) {
            const int k0 = (c + 1) * 32;
            const uint32_t sb2 = sbase + (uint32_t)((c + 1) & 1) * STAGEB;
            #pragma unroll
            for (int mat = 0; mat < 4; mat++) {
                const int rbase = (mat < 2) ? bm : bn;
                cp_async16(sb2 + mat * MATB + (uint32_t)(lrow0 * 80 + lj0 * 16),
                           srcs[mat] + (size_t)(rbase + lrow0) * 512 + k0 + lj0 * 8);
                cp_async16(sb2 + mat * MATB + (uint32_t)(lrow1 * 80 + lj1 * 16),
                           srcs[mat] + (size_t)(rbase + lrow1) * 512 + k0 + lj1 * 8);
            }
            CP_COMMIT();
            CP_WAIT(1);
        } else {
            CP_WAIT(0);
        }
        __syncthreads();

        const uint32_t sA_h = sbase + (uint32_t)stage * STAGEB;
        const uint32_t sA_l = sA_h + MATB;
        const uint32_t sB_h = sA_h + 2 * MATB;
        const uint32_t sB_l = sA_h + 3 * MATB;

        #pragma unroll
        for (int k16 = 0; k16 < 2; k16++) {
            uint32_t ah[4][4], al[4][4], bh[2][4], bl[2][4];
            #pragma unroll
            for (int i = 0; i < 4; i++) {
                uint32_t off = (uint32_t)(wm * 64 + i * 16) * (SPAD * 2)
                             + lrowa + k16 * 32 + lcola;
                ldsm4(ah[i], sA_h + off);
                ldsm4(al[i], sA_l + off);
            }
            #pragma unroll
            for (int j2 = 0; j2 < 2; j2++) {
                uint32_t off = (uint32_t)(wn * 32 + j2 * 16) * (SPAD * 2)
                             + lrowa + k16 * 32 + lcola;
                ldsm4(bh[j2], sB_h + off);
                ldsm4(bl[j2], sB_l + off);
            }
            #pragma unroll
            for (int i = 0; i < 4; i++)
                #pragma unroll
                for (int j2 = 0; j2 < 2; j2++)
                    #pragma unroll
                    for (int s = 0; s < 2; s++) {
                        float* cc = acc[i][j2 * 2 + s];
                        mma_bf16(cc, ah[i], bh[j2][s], bh[j2][s + 2]);
                        mma_bf16(cc, ah[i], bl[j2][s], bl[j2][s + 2]);
                        mma_bf16(cc, al[i], bh[j2][s], bh[j2][s + 2]);
                    }
        }
        __syncthreads();
    }

    // Epilogue
    const int er = lane >> 2;
    const int ec = (lane & 3) * 2;
    #pragma unroll
    for (int i = 0; i < 4; i++) {
        #pragma unroll
        for (int r2 = 0; r2 < 2; r2++) {
            const int m = bm + wm * 64 + i * 16 + er + r2 * 8;
            const int bz = m >> 12, tok = m & 4095;
            const int pemod = tok % MAXPC;
            #pragma unroll
            for (int j = 0; j < 4; j++) {
                #pragma unroll
                for (int r1 = 0; r1 < 2; r1++) {
                    const int col = bn + wn * 32 + j * 8 + ec + r1;
                    const float v0 = acc[i][j][r2 * 2 + r1];
                    if (MODE == 2) {
                        outp[(size_t)m * 512 + col] = v0 + aux[col];
                    } else if (bn < 512) {
                        float v = v0;
                        if (MODE == 1)
                            v += aux[(size_t)pemod * 512 + col];
                        v = v / g_scale[col];
                        const float p = g_power[col];
                        const float aq = fabsf(v);
                        float rr = (aq > 0.f) ? __powf(aq, p) : 0.f;
                        if (v < 0.f) rr = -rr;
                        if (v == 0.f) rr = 0.f;
                        const int h = col >> 6, d = col & 63;
                        float* dst = (MODE == 0 ? g_QQc : g_KKc);
                        dst[((size_t)((bz * NHh + h) * Ntok + tok)) * 64 + d] = rr;
                    } else {
                        float* dst = (MODE == 0 ? g_G : g_V);
                        dst[(size_t)m * 512 + (col - 512)] = v0;
                    }
                }
            }
        }
    }
}

// ---------------------------------------------------------------------------
// K3a: per (chunk, b*h) partial KV = KK^T @ Vhead + colsums
// (KK reconstructed from compact signed form on load)
// ---------------------------------------------------------------------------
__global__ __launch_bounds__(256) void kv_partial() {
    const int chunk = blockIdx.x;
    const int bh    = blockIdx.y;
    const int b = bh >> 3, h = bh & 7;
    __shared__ float KKs[32][128];
    __shared__ float Vs[32][64];
    const int tid = threadIdx.x;
    const int d0 = (tid & 31) << 2;
    const int e0 = (tid >> 5) << 3;

    float acc[4][8];
    #pragma unroll
    for (int i = 0; i < 4; i++)
        #pragma unroll
        for (int j = 0; j < 8; j++) acc[i][j] = 0.f;
    float ks = 0.f;

    const int TPC = Ntok / NCHK;
    const float* KKb = g_KKc + ((size_t)bh * Ntok + (size_t)chunk * TPC) * 64;
    const float* Vb  = g_V + ((size_t)(b * Ntok + chunk * TPC)) * Cch + h * 64;

    for (int t = 0; t < TPC / 32; t++) {
        #pragma unroll
        for (int l = 0; l < 2; l++) {
            int fidx = tid + l * 256;               // 0..511 float4s
            int r = fidx >> 4, d4 = (fidx & 15) << 2;
            float4 rv = *(const float4*)(KKb + (size_t)(t * 32 + r) * 64 + d4);
            KKs[r][d4+0] = fmaxf(rv.x, 0.f); KKs[r][64+d4+0] = fmaxf(-rv.x, 0.f);
            KKs[r][d4+1] = fmaxf(rv.y, 0.f); KKs[r][64+d4+1] = fmaxf(-rv.y, 0.f);
            KKs[r][d4+2] = fmaxf(rv.z, 0.f); KKs[r][64+d4+2] = fmaxf(-rv.z, 0.f);
            KKs[r][d4+3] = fmaxf(rv.w, 0.f); KKs[r][64+d4+3] = fmaxf(-rv.w, 0.f);
        }
        #pragma unroll
        for (int l = 0; l < 2; l++) {
            int fidx = tid + l * 256;
            int r = fidx >> 4, e4 = (fidx & 15) << 2;
            *(float4*)&Vs[r][e4] =
                *(const float4*)(Vb + (size_t)(t * 32 + r) * Cch + e4);
        }
        __syncthreads();
        #pragma unroll
        for (int r = 0; r < 32; r++) {
            float4 a = *(float4*)&KKs[r][d0];
            float4 b0 = *(float4*)&Vs[r][e0];
            float4 b1 = *(float4*)&Vs[r][e0 + 4];
            float av[4] = {a.x, a.y, a.z, a.w};
            float bv[8] = {b0.x, b0.y, b0.z, b0.w, b1.x, b1.y, b1.z, b1.w};
            #pragma unroll
            for (int i = 0; i < 4; i++)
                #pragma unroll
                for (int j = 0; j < 8; j++)
                    acc[i][j] = fmaf(av[i], bv[j], acc[i][j]);
        }
        if (tid < 128) {
            float s = 0.f;
            #pragma unroll
            for (int r = 0; r < 32; r++) s += KKs[r][tid];
            ks += s;
        }
        __syncthreads();
    }

    float* P = g_PKV + ((size_t)(bh * NCHK + chunk) * 128) * 64;
    #pragma unroll
    for (int i = 0; i < 4; i++)
        #pragma unroll
        for (int j = 0; j < 8; j++)
            P[(size_t)(d0 + i) * 64 + e0 + j] = acc[i][j];
    if (tid < 128)
        g_PKS[(size_t)(bh * NCHK + chunk) * 128 + tid] = ks;
}

// ---------------------------------------------------------------------------
// K3b: reduce chunks, build KVC with opp-rotation folded in
// ---------------------------------------------------------------------------
__global__ __launch_bounds__(256) void kv_reduce() {
    const int bh = blockIdx.x;
    const int tid = threadIdx.x;
    const float inv_n = 1.0f / (float)Ntok;
    for (int p = tid; p < 128 * 64; p += 256) {
        int d = p >> 6, e = p & 63;
        int dsrc = (e < 32) ? d : ((d + 64) & 127);
        float s = 0.f;
        #pragma unroll
        for (int c2 = 0; c2 < NCHK; c2++)
            s += g_PKV[((size_t)(bh * NCHK + c2) * 128 + dsrc) * 64 + e];
        g_KVC[(size_t)bh * (128 * 66) + d * 66 + e] = s * inv_n;
    }
    if (tid < 128) {
        int d = tid, dr = (d + 64) & 127;
        float s1 = 0.f, s2 = 0.f;
        #pragma unroll
        for (int c2 = 0; c2 < NCHK; c2++) {
            s1 += g_PKS[(size_t)(bh * NCHK + c2) * 128 + d];
            s2 += g_PKS[(size_t)(bh * NCHK + c2) * 128 + dr];
        }
        g_KVC[(size_t)bh * (128 * 66) + d * 66 + 64] = s1 * inv_n;
        g_KVC[(size_t)bh * (128 * 66) + d * 66 + 65] = s2 * inv_n;
    }
}

// ---------------------------------------------------------------------------
// K4a: per-token z dots (compact QQ)
// ---------------------------------------------------------------------------
__global__ __launch_bounds__(256) void z_kernel() {
    const int bh = blockIdx.y;
    const int tile = blockIdx.x;
    __shared__ float km[128], km2[128];
    const int tid = threadIdx.x;
    const float* __restrict__ KVCb = g_KVC + (size_t)bh * (128 * 66);
    if (tid < 128) {
        km [tid] = KVCb[tid * 66 + 64];
        km2[tid] = KVCb[tid * 66 + 65];
    }
    __syncthreads();
    const int warp = tid >> 5, lane = tid & 31;
    const int d0 = lane * 2;
    for (int it = 0; it < 32; it++) {
        int tok = tile * 256 + warp * 32 + it;
        float2 qv = *(const float2*)(g_QQc + ((size_t)bh * Ntok + tok) * 64 + d0);
        float px = fmaxf(qv.x, 0.f), nx = fmaxf(-qv.x, 0.f);
        float py = fmaxf(qv.y, 0.f), ny = fmaxf(-qv.y, 0.f);
        float p1 = px*km [d0] + nx*km [64+d0] + py*km [d0+1] + ny*km [65+d0];
        float p2 = px*km2[d0] + nx*km2[64+d0] + py*km2[d0+1] + ny*km2[65+d0];
        #pragma unroll
        for (int o = 16; o > 0; o >>= 1) {
            p1 += __shfl_down_sync(0xffffffffu, p1, o);
            p2 += __shfl_down_sync(0xffffffffu, p2, o);
        }
        if (lane == 0)
            g_Z[(size_t)bh * Ntok + tok] = make_float2(p1, p2);
    }
}

// ---------------------------------------------------------------------------
// K4: X = QQ @ KVC (compact A, paired B), fused (x+vd)*g + bf16 split output
// ---------------------------------------------------------------------------
__global__ __launch_bounds__(256) void attn_apply() {
    const int bh = blockIdx.y;
    const int m0 = blockIdx.x * 128;
    const int b = bh >> 3, h = bh & 7;
    __shared__ float As[128][36];      // compact k-slab (32 wide + pad)
    __shared__ float Bs1[32][64];      // KVC[d][:]   for d in slab
    __shared__ float Bs2[32][64];      // KVC[d+64][:]
    const int tid = threadIdx.x;
    const int tm = (tid >> 4) << 3;
    const int tn = (tid & 15) << 2;

    float acc[8][4];
    #pragma unroll
    for (int i = 0; i < 8; i++)
        #pragma unroll
        for (int j = 0; j < 4; j++) acc[i][j] = 0.f;

    const float* Qb = g_QQc + ((size_t)bh * Ntok + m0) * 64;
    const float* KVCb = g_KVC + (size_t)bh * (128 * 66);

    for (int k0 = 0; k0 < 64; k0 += 32) {
        #pragma unroll
        for (int l = 0; l < 4; l++) {
            int fidx = tid + l * 256;        // 1024 float4s = 128 rows x 8
            int row = fidx >> 3, kc = (fidx & 7) << 2;
            *(float4*)&As[row][kc] =
                *(const float4*)(Qb + (size_t)row * 64 + k0 + kc);
        }
        #pragma unroll
        for (int l = 0; l < 8; l++) {
            int idx = tid + l * 256;         // 2048 floats = 32 x 64
            int kk = idx >> 6, n = idx & 63;
            Bs1[kk][n] = KVCb[(k0 + kk) * 66 + n];
            Bs2[kk][n] = KVCb[(k0 + kk + 64) * 66 + n];
        }
        __syncthreads();
        #pragma unroll
        for (int kk = 0; kk < 32; kk++) {
            float4 b1 = *(float4*)&Bs1[kk][tn];
            float4 b2 = *(float4*)&Bs2[kk][tn];
            #pragma unroll
            for (int i = 0; i < 8; i++) {
                float a = As[tm + i][kk];
                float ap = fmaxf(a, 0.f);
                float an = fmaxf(-a, 0.f);
                acc[i][0] = fmaf(ap, b1.x, fmaf(an, b2.x, acc[i][0]));
                acc[i][1] = fmaf(ap, b1.y, fmaf(an, b2.y, acc[i][1]));
                acc[i][2] = fmaf(ap, b1.z, fmaf(an, b2.z, acc[i][2]));
                acc[i][3] = fmaf(ap, b1.w, fmaf(an, b2.w, acc[i][3]));
            }
        }
        __syncthreads();
    }

    #pragma unroll
    for (int i = 0; i < 8; i++) {
        int m = m0 + tm + i;
        float2 z = g_Z[(size_t)bh * Ntok + m];
        float zv = (tn < 32) ? z.x : z.y;
        float inv = 1.0f / (zv + EPSC);
        const size_t off = ((size_t)(b * Ntok + m)) * Cch + h * 64 + tn;
        float4 vd = *(const float4*)(g_VD + off);
        float4 gg = *(const float4*)(g_G + off);
        float r0 = (acc[i][0] * inv + vd.x) * gg.x;
        float r1 = (acc[i][1] * inv + vd.y) * gg.y;
        float r2 = (acc[i][2] * inv + vd.z) * gg.z;
        float r3 = (acc[i][3] * inv + vd.w) * gg.w;
        __nv_bfloat16 h0 = __float2bfloat16(r0), h1 = __float2bfloat16(r1);
        __nv_bfloat16 h2 = __float2bfloat16(r2), h3 = __float2bfloat16(r3);
        __nv_bfloat16 l0 = __float2bfloat16(r0 - __bfloat162float(h0));
        __nv_bfloat16 l1 = __float2bfloat16(r1 - __bfloat162float(h1));
        __nv_bfloat16 l2 = __float2bfloat16(r2 - __bfloat162float(h2));
        __nv_bfloat16 l3 = __float2bfloat16(r3 - __bfloat162float(h3));
        uint2 wh, wl;
        wh.x = (uint32_t)__bfloat16_as_ushort(h0) | ((uint32_t)__bfloat16_as_ushort(h1) << 16);
        wh.y = (uint32_t)__bfloat16_as_ushort(h2) | ((uint32_t)__bfloat16_as_ushort(h3) << 16);
        wl.x = (uint32_t)__bfloat16_as_ushort(l0) | ((uint32_t)__bfloat16_as_ushort(l1) << 16);
        wl.y = (uint32_t)__bfloat16_as_ushort(l2) | ((uint32_t)__bfloat16_as_ushort(l3) << 16);
        *(uint2*)(g_XAh + off) = wh;
        *(uint2*)(g_XAl + off) = wl;
    }
}

// ---------------------------------------------------------------------------
// K5: depthwise 5x5 conv on the (c2, y, x2) view of v
// ---------------------------------------------------------------------------
__global__ __launch_bounds__(256) void dwconv(const float* __restrict__ Wc,
                                              const float* __restrict__ Bc) {
    const int ytile = blockIdx.x;
    const int c2 = blockIdx.y;
    const int b  = blockIdx.z;
    __shared__ float sIn[132][12];
    __shared__ float sW[25];
    __shared__ float sB;
    const int tid = threadIdx.x;
    if (tid < 25) sW[tid] = Wc[c2 * 25 + tid];
    if (tid == 25) sB = Bc[c2];
    const int y0 = ytile * 128;
    const int h = c2 >> 3;
    const int nhi = (c2 & 7) * 512;

    for (int idx = tid; idx < 132 * 12; idx += 256) {
        int sy = idx / 12, sx = idx % 12;
        int yy = y0 - 2 + sy;
        int xx = sx - 2;
        float v = 0.f;
        if (xx >= 0 && xx < 8 && yy >= 0 && yy < 4096) {
            int n = nhi + (yy >> 3);
            int d = ((yy & 7) << 3) + xx;
            v = g_V[((size_t)(b * Ntok + n)) * Cch + h * 64 + d];
        }
        sIn[sy][sx] = v;
    }
    __syncthreads();

    const int x2 = tid & 7;
    const int yl0 = tid >> 3;
    #pragma unroll
    for (int j = 0; j < 4; j++) {
        int yl = yl0 + j * 32;
        float a = sB;
        #pragma unroll
        for (int dy = 0; dy < 5; dy++)
            #pragma unroll
            for (int dx = 0; dx < 5; dx++)
                a = fmaf(sW[dy * 5 + dx], sIn[yl + dy][x2 + dx], a);
        int y = y0 + yl;
        int cc = c2 * 8 + (y >> 9);
        int nn = ((y & 511) << 3) + x2;
        g_VD[((size_t)(b * Ntok + nn)) * Cch + cc] = a;
    }
}

// ---------------------------------------------------------------------------
extern "C" void kernel_launch(void* const* d_in, const int* in_sizes, int n_in,
                              void* d_out, int out_size) {
    const float* x       = (const float*)d_in[0];
    const float* qg_w    = (const float*)d_in[1];
    const float* kv_w    = (const float*)d_in[2];
    const float* proj_w  = (const float*)d_in[3];
    const float* proj_b  = (const float*)d_in[4];
    const float* power_p = (const float*)d_in[5];
    const float* scale_p = (const float*)d_in[6];
    const float* pos_emb = (const float*)d_in[7];
    const float* dwc_w   = (const float*)d_in[8];
    const float* dwc_b   = (const float*)d_in[9];
    float* out = (float*)d_out;

    __nv_bfloat16 *p_Xh, *p_Xl, *p_XAh, *p_XAl;
    __nv_bfloat16 *p_Wqgh, *p_Wqgl, *p_Wkvh, *p_Wkvl, *p_Wph, *p_Wpl;
    cudaGetSymbolAddress((void**)&p_Xh,  g_Xh);
    cudaGetSymbolAddress((void**)&p_Xl,  g_Xl);
    cudaGetSymbolAddress((void**)&p_XAh, g_XAh);
    cudaGetSymbolAddress((void**)&p_XAl, g_XAl);
    cudaGetSymbolAddress((void**)&p_Wqgh, g_Wqgh);
    cudaGetSymbolAddress((void**)&p_Wqgl, g_Wqgl);
    cudaGetSymbolAddress((void**)&p_Wkvh, g_Wkvh);
    cudaGetSymbolAddress((void**)&p_Wkvl, g_Wkvl);
    cudaGetSymbolAddress((void**)&p_Wph, g_Wph);
    cudaGetSymbolAddress((void**)&p_Wpl, g_Wpl);

    cudaFuncSetAttribute(tc_gemm<0>, cudaFuncAttributeMaxDynamicSharedMemorySize, TCSMEM);
    cudaFuncSetAttribute(tc_gemm<1>, cudaFuncAttributeMaxDynamicSharedMemorySize, TCSMEM);
    cudaFuncSetAttribute(tc_gemm<2>, cudaFuncAttributeMaxDynamicSharedMemorySize, TCSMEM);

    prep_kernel<<<1, 512>>>(scale_p, power_p);
    split_kernel<<<16384, 256>>>(x, p_Xh, p_Xl, Bsz * Ntok * Cch / 4);
    split_kernel<<<512, 256>>>(qg_w, p_Wqgh, p_Wqgl, 2 * Cch * Cch / 4);
    split_kernel<<<512, 256>>>(kv_w, p_Wkvh, p_Wkvl, 2 * Cch * Cch / 4);
    split_kernel<<<256, 256>>>(proj_w, p_Wph, p_Wpl, Cch * Cch / 4);

    tc_gemm<0><<<dim3(8, 256), 256, TCSMEM>>>(p_Xh, p_Xl, p_Wqgh, p_Wqgl, nullptr, nullptr);
    tc_gemm<1><<<dim3(8, 256), 256, TCSMEM>>>(p_Xh, p_Xl, p_Wkvh, p_Wkvl, pos_emb, nullptr);

    kv_partial<<<dim3(NCHK, 64), 256>>>();
    kv_reduce<<<64, 256>>>();
    z_kernel<<<dim3(16, 64), 256>>>();
    dwconv<<<dim3(32, 64, 8), 256>>>(dwc_w, dwc_b);
    attn_apply<<<dim3(32, 64), 256>>>();

    tc_gemm<2><<<dim3(4, 256), 256, TCSMEM>>>(p_XAh, p_XAl, p_Wph, p_Wpl, proj_b, out);
}

// round 10
// speedup vs baseline: 2.7782x; 1.4398x over previous
#include <cuda_runtime.h>
#include <cuda_fp16.h>
#include <math.h>
#include <stdint.h>

// Problem constants
#define Bsz   8
#define Ntok  4096
#define Cch   512
#define NHh   8
#define HDd   64
#define MAXPC 321
#define EPSC  1e-6f
#define NCHK  16

// ---------------------------------------------------------------------------
// Scratch (device globals)
// ---------------------------------------------------------------------------
static __device__ float g_QQc[Bsz*NHh*Ntok*64];   // compact signed |q|^p
static __device__ float g_KKc[Bsz*NHh*Ntok*64];   // compact signed |k|^p
static __device__ float g_G [Bsz*Ntok*Cch];
static __device__ float g_V [Bsz*Ntok*Cch];
static __device__ float g_VD[Bsz*Ntok*Cch];
static __device__ float g_PKV[Bsz*NHh*NCHK*128*64];
static __device__ float g_PKS[Bsz*NHh*NCHK*128];
static __device__ float g_KVC[Bsz*NHh*128*66];
static __device__ float2 g_Z [Bsz*NHh*Ntok];
static __device__ float g_scale[Cch];
static __device__ float g_power[Cch];
// fp16 operands
static __device__ __half g_Xf [Bsz*Ntok*Cch];
static __device__ __half g_XAf[Bsz*Ntok*Cch];
static __device__ __half g_Wqgf[2*Cch*Cch];
static __device__ __half g_Wkvf[2*Cch*Cch];
static __device__ __half g_Wpf [Cch*Cch];

// ---------------------------------------------------------------------------
// mma.sync / cp.async helpers (sm_80-compatible PTX)
// ---------------------------------------------------------------------------
__device__ __forceinline__ uint32_t smem_u32(const void* p) {
    uint32_t a;
    asm("{ .reg .u64 t; cvta.to.shared.u64 t, %1; cvt.u32.u64 %0, t; }"
        : "=r"(a) : "l"(p));
    return a;
}
__device__ __forceinline__ void ldsm4(uint32_t* r, uint32_t addr) {
    asm volatile("ldmatrix.sync.aligned.m8n8.x4.shared.b16 {%0,%1,%2,%3}, [%4];"
        : "=r"(r[0]), "=r"(r[1]), "=r"(r[2]), "=r"(r[3]) : "r"(addr));
}
__device__ __forceinline__ void mma_f16(float* c, const uint32_t* a,
                                        uint32_t b0, uint32_t b1) {
    asm volatile("mma.sync.aligned.m16n8k16.row.col.f32.f16.f16.f32 "
        "{%0,%1,%2,%3}, {%4,%5,%6,%7}, {%8,%9}, {%0,%1,%2,%3};"
        : "+f"(c[0]), "+f"(c[1]), "+f"(c[2]), "+f"(c[3])
        : "r"(a[0]), "r"(a[1]), "r"(a[2]), "r"(a[3]), "r"(b0), "r"(b1));
}
__device__ __forceinline__ void cp_async16(uint32_t daddr, const void* gptr) {
    asm volatile("cp.async.cg.shared.global [%0], [%1], 16;"
                 :: "r"(daddr), "l"(gptr) : "memory");
}
#define CP_COMMIT() asm volatile("cp.async.commit_group;" ::: "memory")
#define CP_WAIT(N)  asm volatile("cp.async.wait_group %0;" :: "n"(N) : "memory")

// ---------------------------------------------------------------------------
// K0: precompute softplus(scale_p), 1+4*sigmoid(power_p)
// ---------------------------------------------------------------------------
__global__ void prep_kernel(const float* __restrict__ scale_p,
                            const float* __restrict__ power_p) {
    int i = threadIdx.x;
    if (i < Cch) {
        float sp = scale_p[i];
        g_scale[i] = (sp > 20.f) ? sp : log1pf(expf(sp));
        float pp = power_p[i];
        g_power[i] = 1.0f + 4.0f / (1.0f + expf(-pp));
    }
}

// ---------------------------------------------------------------------------
// Convert fp32 -> fp16
// ---------------------------------------------------------------------------
__global__ __launch_bounds__(256) void cvt_kernel(
    const float* __restrict__ src, __half* __restrict__ dst, int n4)
{
    int i = blockIdx.x * 256 + threadIdx.x;
    if (i >= n4) return;
    float4 v = ((const float4*)src)[i];
    __half2 a = __floats2half2_rn(v.x, v.y);
    __half2 b = __floats2half2_rn(v.z, v.w);
    uint2 w;
    w.x = *(uint32_t*)&a;
    w.y = *(uint32_t*)&b;
    ((uint2*)dst)[i] = w;
}

// ---------------------------------------------------------------------------
// Tensor GEMM via fp16 mma.sync + cp.async double buffering.
// C[m][c] = sum_k A[m][k]*B[c][k], K=512, single fp16 MMA (inputs fp16,
// fp32 accumulate). Block 128x128, 8 warps (2x4), warp tile 64x32,
// K-chunk 32, 2 stages.
// MODE 0: qg (compact signed QQc + G)  MODE 1: kv (KKc + V)  MODE 2: proj
// ---------------------------------------------------------------------------
#define SPAD 40                     // smem row stride in halves (80B)
#define MATB (128 * SPAD * 2)       // 10240 B per matrix tile
#define STAGEB (2 * MATB)           // 20480 B per stage (A + B)
#define TCSMEM (2 * STAGEB)         // 40960 B total

template<int MODE>
__global__ __launch_bounds__(256) void tc_gemm(
    const __half* __restrict__ A_g, const __half* __restrict__ B_g,
    const float* __restrict__ aux, float* __restrict__ outp)
{
    extern __shared__ __half dsm[];
    const uint32_t sbase = smem_u32(dsm);
    const int tid = threadIdx.x;
    const int wid = tid >> 5;
    const int lane = tid & 31;
    const int wm = wid >> 2;
    const int wn = wid & 3;
    const int bm = blockIdx.y * 128;
    const int bn = blockIdx.x * 128;

    float acc[4][4][4];
    #pragma unroll
    for (int i = 0; i < 4; i++)
        #pragma unroll
        for (int j = 0; j < 4; j++)
            #pragma unroll
            for (int r = 0; r < 4; r++) acc[i][j][r] = 0.f;

    // loads: per chunk per matrix 512 x 16B; 2 matrices = 1024 ops / 256 thr
    const int lrow0 = tid >> 2, lj0 = tid & 3;
    const int lrow1 = (tid + 256) >> 2, lj1 = tid & 3;
    const uint32_t lrowa = (uint32_t)(lane & 15) * (SPAD * 2);
    const uint32_t lcola = (uint32_t)(lane >> 4) * 16;

    const __half* srcs[2] = {A_g, B_g};

    {
        #pragma unroll
        for (int mat = 0; mat < 2; mat++) {
            const int rbase = (mat == 0) ? bm : bn;
            cp_async16(sbase + mat * MATB + (uint32_t)(lrow0 * 80 + lj0 * 16),
                       srcs[mat] + (size_t)(rbase + lrow0) * 512 + lj0 * 8);
            cp_async16(sbase + mat * MATB + (uint32_t)(lrow1 * 80 + lj1 * 16),
                       srcs[mat] + (size_t)(rbase + lrow1) * 512 + lj1 * 8);
        }
        CP_COMMIT();
    }

    for (int c = 0; c < 16; c++) {
        const int stage = c & 1;
        if (c + 1 < 16) {
            const int k0 = (c + 1) * 32;
            const uint32_t sb2 = sbase + (uint32_t)((c + 1) & 1) * STAGEB;
            #pragma unroll
            for (int mat = 0; mat < 2; mat++) {
                const int rbase = (mat == 0) ? bm : bn;
                cp_async16(sb2 + mat * MATB + (uint32_t)(lrow0 * 80 + lj0 * 16),
                           srcs[mat] + (size_t)(rbase + lrow0) * 512 + k0 + lj0 * 8);
                cp_async16(sb2 + mat * MATB + (uint32_t)(lrow1 * 80 + lj1 * 16),
                           srcs[mat] + (size_t)(rbase + lrow1) * 512 + k0 + lj1 * 8);
            }
            CP_COMMIT();
            CP_WAIT(1);
        } else {
            CP_WAIT(0);
        }
        __syncthreads();

        const uint32_t sA = sbase + (uint32_t)stage * STAGEB;
        const uint32_t sB = sA + MATB;

        #pragma unroll
        for (int k16 = 0; k16 < 2; k16++) {
            uint32_t ah[4][4], bh[2][4];
            #pragma unroll
            for (int i = 0; i < 4; i++) {
                uint32_t off = (uint32_t)(wm * 64 + i * 16) * (SPAD * 2)
                             + lrowa + k16 * 32 + lcola;
                ldsm4(ah[i], sA + off);
            }
            #pragma unroll
            for (int j2 = 0; j2 < 2; j2++) {
                uint32_t off = (uint32_t)(wn * 32 + j2 * 16) * (SPAD * 2)
                             + lrowa + k16 * 32 + lcola;
                ldsm4(bh[j2], sB + off);
            }
            #pragma unroll
            for (int i = 0; i < 4; i++)
                #pragma unroll
                for (int j2 = 0; j2 < 2; j2++)
                    #pragma unroll
                    for (int s = 0; s < 2; s++)
                        mma_f16(acc[i][j2 * 2 + s], ah[i],
                                bh[j2][s], bh[j2][s + 2]);
        }
        __syncthreads();
    }

    // Epilogue
    const int er = lane >> 2;
    const int ec = (lane & 3) * 2;
    #pragma unroll
    for (int i = 0; i < 4; i++) {
        #pragma unroll
        for (int r2 = 0; r2 < 2; r2++) {
            const int m = bm + wm * 64 + i * 16 + er + r2 * 8;
            const int bz = m >> 12, tok = m & 4095;
            const int pemod = tok % MAXPC;
            #pragma unroll
            for (int j = 0; j < 4; j++) {
                #pragma unroll
                for (int r1 = 0; r1 < 2; r1++) {
                    const int col = bn + wn * 32 + j * 8 + ec + r1;
                    const float v0 = acc[i][j][r2 * 2 + r1];
                    if (MODE == 2) {
                        outp[(size_t)m * 512 + col] = v0 + aux[col];
                    } else if (bn < 512) {
                        float v = v0;
                        if (MODE == 1)
                            v += aux[(size_t)pemod * 512 + col];
                        v = v / g_scale[col];
                        const float p = g_power[col];
                        const float aq = fabsf(v);
                        float rr = (aq > 0.f) ? __powf(aq, p) : 0.f;
                        if (v < 0.f) rr = -rr;
                        if (v == 0.f) rr = 0.f;
                        const int h = col >> 6, d = col & 63;
                        float* dst = (MODE == 0 ? g_QQc : g_KKc);
                        dst[((size_t)((bz * NHh + h) * Ntok + tok)) * 64 + d] = rr;
                    } else {
                        float* dst = (MODE == 0 ? g_G : g_V);
                        dst[(size_t)m * 512 + (col - 512)] = v0;
                    }
                }
            }
        }
    }
}

// ---------------------------------------------------------------------------
// K3a: per (chunk, b*h) partial KV = KK^T @ Vhead + colsums
// ---------------------------------------------------------------------------
__global__ __launch_bounds__(256) void kv_partial() {
    const int chunk = blockIdx.x;
    const int bh    = blockIdx.y;
    const int b = bh >> 3, h = bh & 7;
    __shared__ float KKs[32][128];
    __shared__ float Vs[32][64];
    const int tid = threadIdx.x;
    const int d0 = (tid & 31) << 2;
    const int e0 = (tid >> 5) << 3;

    float acc[4][8];
    #pragma unroll
    for (int i = 0; i < 4; i++)
        #pragma unroll
        for (int j = 0; j < 8; j++) acc[i][j] = 0.f;
    float ks = 0.f;

    const int TPC = Ntok / NCHK;
    const float* KKb = g_KKc + ((size_t)bh * Ntok + (size_t)chunk * TPC) * 64;
    const float* Vb  = g_V + ((size_t)(b * Ntok + chunk * TPC)) * Cch + h * 64;

    for (int t = 0; t < TPC / 32; t++) {
        #pragma unroll
        for (int l = 0; l < 2; l++) {
            int fidx = tid + l * 256;
            int r = fidx >> 4, d4 = (fidx & 15) << 2;
            float4 rv = *(const float4*)(KKb + (size_t)(t * 32 + r) * 64 + d4);
            KKs[r][d4+0] = fmaxf(rv.x, 0.f); KKs[r][64+d4+0] = fmaxf(-rv.x, 0.f);
            KKs[r][d4+1] = fmaxf(rv.y, 0.f); KKs[r][64+d4+1] = fmaxf(-rv.y, 0.f);
            KKs[r][d4+2] = fmaxf(rv.z, 0.f); KKs[r][64+d4+2] = fmaxf(-rv.z, 0.f);
            KKs[r][d4+3] = fmaxf(rv.w, 0.f); KKs[r][64+d4+3] = fmaxf(-rv.w, 0.f);
        }
        #pragma unroll
        for (int l = 0; l < 2; l++) {
            int fidx = tid + l * 256;
            int r = fidx >> 4, e4 = (fidx & 15) << 2;
            *(float4*)&Vs[r][e4] =
                *(const float4*)(Vb + (size_t)(t * 32 + r) * Cch + e4);
        }
        __syncthreads();
        #pragma unroll
        for (int r = 0; r < 32; r++) {
            float4 a = *(float4*)&KKs[r][d0];
            float4 b0 = *(float4*)&Vs[r][e0];
            float4 b1 = *(float4*)&Vs[r][e0 + 4];
            float av[4] = {a.x, a.y, a.z, a.w};
            float bv[8] = {b0.x, b0.y, b0.z, b0.w, b1.x, b1.y, b1.z, b1.w};
            #pragma unroll
            for (int i = 0; i < 4; i++)
                #pragma unroll
                for (int j = 0; j < 8; j++)
                    acc[i][j] = fmaf(av[i], bv[j], acc[i][j]);
        }
        if (tid < 128) {
            float s = 0.f;
            #pragma unroll
            for (int r = 0; r < 32; r++) s += KKs[r][tid];
            ks += s;
        }
        __syncthreads();
    }

    float* P = g_PKV + ((size_t)(bh * NCHK + chunk) * 128) * 64;
    #pragma unroll
    for (int i = 0; i < 4; i++)
        #pragma unroll
        for (int j = 0; j < 8; j++)
            P[(size_t)(d0 + i) * 64 + e0 + j] = acc[i][j];
    if (tid < 128)
        g_PKS[(size_t)(bh * NCHK + chunk) * 128 + tid] = ks;
}

// ---------------------------------------------------------------------------
// K3b: reduce chunks, build KVC with opp-rotation folded in
// ---------------------------------------------------------------------------
__global__ __launch_bounds__(256) void kv_reduce() {
    const int bh = blockIdx.x;
    const int tid = threadIdx.x;
    const float inv_n = 1.0f / (float)Ntok;
    for (int p = tid; p < 128 * 64; p += 256) {
        int d = p >> 6, e = p & 63;
        int dsrc = (e < 32) ? d : ((d + 64) & 127);
        float s = 0.f;
        #pragma unroll
        for (int c2 = 0; c2 < NCHK; c2++)
            s += g_PKV[((size_t)(bh * NCHK + c2) * 128 + dsrc) * 64 + e];
        g_KVC[(size_t)bh * (128 * 66) + d * 66 + e] = s * inv_n;
    }
    if (tid < 128) {
        int d = tid, dr = (d + 64) & 127;
        float s1 = 0.f, s2 = 0.f;
        #pragma unroll
        for (int c2 = 0; c2 < NCHK; c2++) {
            s1 += g_PKS[(size_t)(bh * NCHK + c2) * 128 + d];
            s2 += g_PKS[(size_t)(bh * NCHK + c2) * 128 + dr];
        }
        g_KVC[(size_t)bh * (128 * 66) + d * 66 + 64] = s1 * inv_n;
        g_KVC[(size_t)bh * (128 * 66) + d * 66 + 65] = s2 * inv_n;
    }
}

// ---------------------------------------------------------------------------
// K4a: per-token z dots (compact QQ)
// ---------------------------------------------------------------------------
__global__ __launch_bounds__(256) void z_kernel() {
    const int bh = blockIdx.y;
    const int tile = blockIdx.x;
    __shared__ float km[128], km2[128];
    const int tid = threadIdx.x;
    const float* __restrict__ KVCb = g_KVC + (size_t)bh * (128 * 66);
    if (tid < 128) {
        km [tid] = KVCb[tid * 66 + 64];
        km2[tid] = KVCb[tid * 66 + 65];
    }
    __syncthreads();
    const int warp = tid >> 5, lane = tid & 31;
    const int d0 = lane * 2;
    for (int it = 0; it < 32; it++) {
        int tok = tile * 256 + warp * 32 + it;
        float2 qv = *(const float2*)(g_QQc + ((size_t)bh * Ntok + tok) * 64 + d0);
        float px = fmaxf(qv.x, 0.f), nx = fmaxf(-qv.x, 0.f);
        float py = fmaxf(qv.y, 0.f), ny = fmaxf(-qv.y, 0.f);
        float p1 = px*km [d0] + nx*km [64+d0] + py*km [d0+1] + ny*km [65+d0];
        float p2 = px*km2[d0] + nx*km2[64+d0] + py*km2[d0+1] + ny*km2[65+d0];
        #pragma unroll
        for (int o = 16; o > 0; o >>= 1) {
            p1 += __shfl_down_sync(0xffffffffu, p1, o);
            p2 += __shfl_down_sync(0xffffffffu, p2, o);
        }
        if (lane == 0)
            g_Z[(size_t)bh * Ntok + tok] = make_float2(p1, p2);
    }
}

// ---------------------------------------------------------------------------
// K4: X = QQ @ KVC (compact A, paired B), fused (x+vd)*g -> fp16 XA
// ---------------------------------------------------------------------------
__global__ __launch_bounds__(256) void attn_apply() {
    const int bh = blockIdx.y;
    const int m0 = blockIdx.x * 128;
    const int b = bh >> 3, h = bh & 7;
    __shared__ float As[128][36];
    __shared__ float Bs1[32][64];
    __shared__ float Bs2[32][64];
    const int tid = threadIdx.x;
    const int tm = (tid >> 4) << 3;
    const int tn = (tid & 15) << 2;

    float acc[8][4];
    #pragma unroll
    for (int i = 0; i < 8; i++)
        #pragma unroll
        for (int j = 0; j < 4; j++) acc[i][j] = 0.f;

    const float* Qb = g_QQc + ((size_t)bh * Ntok + m0) * 64;
    const float* KVCb = g_KVC + (size_t)bh * (128 * 66);

    for (int k0 = 0; k0 < 64; k0 += 32) {
        #pragma unroll
        for (int l = 0; l < 4; l++) {
            int fidx = tid + l * 256;
            int row = fidx >> 3, kc = (fidx & 7) << 2;
            *(float4*)&As[row][kc] =
                *(const float4*)(Qb + (size_t)row * 64 + k0 + kc);
        }
        #pragma unroll
        for (int l = 0; l < 8; l++) {
            int idx = tid + l * 256;
            int kk = idx >> 6, n = idx & 63;
            Bs1[kk][n] = KVCb[(k0 + kk) * 66 + n];
            Bs2[kk][n] = KVCb[(k0 + kk + 64) * 66 + n];
        }
        __syncthreads();
        #pragma unroll
        for (int kk = 0; kk < 32; kk++) {
            float4 b1 = *(float4*)&Bs1[kk][tn];
            float4 b2 = *(float4*)&Bs2[kk][tn];
            #pragma unroll
            for (int i = 0; i < 8; i++) {
                float a = As[tm + i][kk];
                float ap = fmaxf(a, 0.f);
                float an = fmaxf(-a, 0.f);
                acc[i][0] = fmaf(ap, b1.x, fmaf(an, b2.x, acc[i][0]));
                acc[i][1] = fmaf(ap, b1.y, fmaf(an, b2.y, acc[i][1]));
                acc[i][2] = fmaf(ap, b1.z, fmaf(an, b2.z, acc[i][2]));
                acc[i][3] = fmaf(ap, b1.w, fmaf(an, b2.w, acc[i][3]));
            }
        }
        __syncthreads();
    }

    #pragma unroll
    for (int i = 0; i < 8; i++) {
        int m = m0 + tm + i;
        float2 z = g_Z[(size_t)bh * Ntok + m];
        float zv = (tn < 32) ? z.x : z.y;
        float inv = 1.0f / (zv + EPSC);
        const size_t off = ((size_t)(b * Ntok + m)) * Cch + h * 64 + tn;
        float4 vd = *(const float4*)(g_VD + off);
        float4 gg = *(const float4*)(g_G + off);
        float r0 = (acc[i][0] * inv + vd.x) * gg.x;
        float r1 = (acc[i][1] * inv + vd.y) * gg.y;
        float r2 = (acc[i][2] * inv + vd.z) * gg.z;
        float r3 = (acc[i][3] * inv + vd.w) * gg.w;
        __half2 pa = __floats2half2_rn(r0, r1);
        __half2 pb = __floats2half2_rn(r2, r3);
        uint2 w;
        w.x = *(uint32_t*)&pa;
        w.y = *(uint32_t*)&pb;
        *(uint2*)(g_XAf + off) = w;
    }
}

// ---------------------------------------------------------------------------
// K5: depthwise 5x5 conv on the (c2, y, x2) view of v
// ---------------------------------------------------------------------------
__global__ __launch_bounds__(256) void dwconv(const float* __restrict__ Wc,
                                              const float* __restrict__ Bc) {
    const int ytile = blockIdx.x;
    const int c2 = blockIdx.y;
    const int b  = blockIdx.z;
    __shared__ float sIn[132][12];
    __shared__ float sW[25];
    __shared__ float sB;
    const int tid = threadIdx.x;
    if (tid < 25) sW[tid] = Wc[c2 * 25 + tid];
    if (tid == 25) sB = Bc[c2];
    const int y0 = ytile * 128;
    const int h = c2 >> 3;
    const int nhi = (c2 & 7) * 512;

    for (int idx = tid; idx < 132 * 12; idx += 256) {
        int sy = idx / 12, sx = idx % 12;
        int yy = y0 - 2 + sy;
        int xx = sx - 2;
        float v = 0.f;
        if (xx >= 0 && xx < 8 && yy >= 0 && yy < 4096) {
            int n = nhi + (yy >> 3);
            int d = ((yy & 7) << 3) + xx;
            v = g_V[((size_t)(b * Ntok + n)) * Cch + h * 64 + d];
        }
        sIn[sy][sx] = v;
    }
    __syncthreads();

    const int x2 = tid & 7;
    const int yl0 = tid >> 3;
    #pragma unroll
    for (int j = 0; j < 4; j++) {
        int yl = yl0 + j * 32;
        float a = sB;
        #pragma unroll
        for (int dy = 0; dy < 5; dy++)
            #pragma unroll
            for (int dx = 0; dx < 5; dx++)
                a = fmaf(sW[dy * 5 + dx], sIn[yl + dy][x2 + dx], a);
        int y = y0 + yl;
        int cc = c2 * 8 + (y >> 9);
        int nn = ((y & 511) << 3) + x2;
        g_VD[((size_t)(b * Ntok + nn)) * Cch + cc] = a;
    }
}

// ---------------------------------------------------------------------------
extern "C" void kernel_launch(void* const* d_in, const int* in_sizes, int n_in,
                              void* d_out, int out_size) {
    const float* x       = (const float*)d_in[0];
    const float* qg_w    = (const float*)d_in[1];
    const float* kv_w    = (const float*)d_in[2];
    const float* proj_w  = (const float*)d_in[3];
    const float* proj_b  = (const float*)d_in[4];
    const float* power_p = (const float*)d_in[5];
    const float* scale_p = (const float*)d_in[6];
    const float* pos_emb = (const float*)d_in[7];
    const float* dwc_w   = (const float*)d_in[8];
    const float* dwc_b   = (const float*)d_in[9];
    float* out = (float*)d_out;

    __half *p_Xf, *p_XAf, *p_Wqgf, *p_Wkvf, *p_Wpf;
    cudaGetSymbolAddress((void**)&p_Xf,   g_Xf);
    cudaGetSymbolAddress((void**)&p_XAf,  g_XAf);
    cudaGetSymbolAddress((void**)&p_Wqgf, g_Wqgf);
    cudaGetSymbolAddress((void**)&p_Wkvf, g_Wkvf);
    cudaGetSymbolAddress((void**)&p_Wpf,  g_Wpf);

    cudaFuncSetAttribute(tc_gemm<0>, cudaFuncAttributeMaxDynamicSharedMemorySize, TCSMEM);
    cudaFuncSetAttribute(tc_gemm<1>, cudaFuncAttributeMaxDynamicSharedMemorySize, TCSMEM);
    cudaFuncSetAttribute(tc_gemm<2>, cudaFuncAttributeMaxDynamicSharedMemorySize, TCSMEM);

    prep_kernel<<<1, 512>>>(scale_p, power_p);
    cvt_kernel<<<16384, 256>>>(x, p_Xf, Bsz * Ntok * Cch / 4);
    cvt_kernel<<<512, 256>>>(qg_w, p_Wqgf, 2 * Cch * Cch / 4);
    cvt_kernel<<<512, 256>>>(kv_w, p_Wkvf, 2 * Cch * Cch / 4);
    cvt_kernel<<<256, 256>>>(proj_w, p_Wpf, Cch * Cch / 4);

    tc_gemm<0><<<dim3(8, 256), 256, TCSMEM>>>(p_Xf, p_Wqgf, nullptr, nullptr);
    tc_gemm<1><<<dim3(8, 256), 256, TCSMEM>>>(p_Xf, p_Wkvf, pos_emb, nullptr);

    kv_partial<<<dim3(NCHK, 64), 256>>>();
    kv_reduce<<<64, 256>>>();
    z_kernel<<<dim3(16, 64), 256>>>();
    dwconv<<<dim3(32, 64, 8), 256>>>(dwc_w, dwc_b);
    attn_apply<<<dim3(32, 64), 256>>>();

    tc_gemm<2><<<dim3(4, 256), 256, TCSMEM>>>(p_XAf, p_Wpf, proj_b, out);
}